// round 2
// baseline (speedup 1.0000x reference)
#include <cuda_runtime.h>
#include <cuda_bf16.h>
#include <math.h>

// Problem constants
#define BB   2
#define SS   2048
#define DD   1024
#define HH   16
#define DHH  64
#define DMM  4096
#define NTOK (BB*SS)          // 4096
#define EPSLN 1e-5f

// ---------------------------------------------------------------------------
// Device scratch (allocation-free rule: use __device__ globals)
// ---------------------------------------------------------------------------
__device__ float g_xn [NTOK*DD];        // LN output (reused for LN1 and LN2)
__device__ float g_q  [NTOK*DD];
__device__ float g_k  [NTOK*DD];
__device__ float g_v  [NTOK*DD];
__device__ float g_z  [NTOK*DD];
__device__ float g_mid[NTOK*DD];        // resid_mid
__device__ float g_act[NTOK*DMM];       // gelu(mlp pre)
__device__ float g_wt [DD*DD];          // transposed QKV weight scratch

// ---------------------------------------------------------------------------
// LayerNorm: one block per row, 256 threads, 4 floats (one float4) per thread
// ---------------------------------------------------------------------------
__global__ __launch_bounds__(256)
void ln_kernel(const float* __restrict__ x, const float* __restrict__ w,
               const float* __restrict__ b, float* __restrict__ out)
{
    __shared__ float red[8];
    __shared__ float bcast;
    const int row = blockIdx.x;
    const int tid = threadIdx.x;
    const int lane = tid & 31, warp = tid >> 5;

    float4 v = ((const float4*)(x + (size_t)row * DD))[tid];

    // --- sum reduce ---
    float s = v.x + v.y + v.z + v.w;
    #pragma unroll
    for (int o = 16; o > 0; o >>= 1) s += __shfl_xor_sync(0xffffffffu, s, o);
    if (lane == 0) red[warp] = s;
    __syncthreads();
    if (tid < 8) {
        float t = red[tid];
        #pragma unroll
        for (int o = 4; o > 0; o >>= 1) t += __shfl_xor_sync(0xffu, t, o);
        if (tid == 0) bcast = t;
    }
    __syncthreads();
    const float mean = bcast * (1.0f / DD);
    __syncthreads();

    // --- centered sumsq reduce ---
    float dx0 = v.x - mean, dx1 = v.y - mean, dx2 = v.z - mean, dx3 = v.w - mean;
    float sq = dx0*dx0 + dx1*dx1 + dx2*dx2 + dx3*dx3;
    #pragma unroll
    for (int o = 16; o > 0; o >>= 1) sq += __shfl_xor_sync(0xffffffffu, sq, o);
    if (lane == 0) red[warp] = sq;
    __syncthreads();
    if (tid < 8) {
        float t = red[tid];
        #pragma unroll
        for (int o = 4; o > 0; o >>= 1) t += __shfl_xor_sync(0xffu, t, o);
        if (tid == 0) bcast = t;
    }
    __syncthreads();
    const float var = bcast * (1.0f / DD);
    const float inv = rsqrtf(var + EPSLN);

    float4 wv = ((const float4*)w)[tid];
    float4 bv = ((const float4*)b)[tid];
    float4 o4;
    o4.x = dx0 * inv * wv.x + bv.x;
    o4.y = dx1 * inv * wv.y + bv.y;
    o4.z = dx2 * inv * wv.z + bv.z;
    o4.w = dx3 * inv * wv.w + bv.w;
    ((float4*)(out + (size_t)row * DD))[tid] = o4;
}

// ---------------------------------------------------------------------------
// QKV weight transpose: [H][D][DH] -> [D][H*DH]
// ---------------------------------------------------------------------------
__global__ __launch_bounds__(256)
void qkvw_transpose(const float* __restrict__ w, float* __restrict__ wt)
{
    int f4 = blockIdx.x * blockDim.x + threadIdx.x;   // 0 .. 262143
    int f  = f4 * 4;
    int h  = f >> 16;          // / (D*DH) = /65536
    int r  = f & 65535;
    int d  = r >> 6;
    int m  = r & 63;
    float4 v = *(const float4*)(w + f);
    *(float4*)(wt + d * DD + h * DHH + m) = v;
}

// ---------------------------------------------------------------------------
// Tiled SGEMM: C[M,N] = A[M,K] @ B[K,N] (+bias +residual/gelu per EPI)
// BM=BN=128, BK=8, 256 threads, 8x8 micro-tile.
// EPI: 0 = bias  1 = bias+gelu  2 = bias+residual
// ---------------------------------------------------------------------------
#define EPI_BIAS       0
#define EPI_BIAS_GELU  1
#define EPI_BIAS_RES   2

__device__ __forceinline__ float gelu_exact(float x)
{
    return 0.5f * x * (1.0f + erff(x * 0.70710678118654752f));
}

template <int EPI>
__global__ __launch_bounds__(256)
void sgemm_kernel(const float* __restrict__ A, const float* __restrict__ Bm,
                  const float* __restrict__ bias, const float* __restrict__ Rm,
                  float* __restrict__ C, int M, int N, int K)
{
    __shared__ float As[8][128];
    __shared__ float Bs[8][128];

    const int tid  = threadIdx.x;
    const int row0 = blockIdx.y * 128;
    const int col0 = blockIdx.x * 128;

    const int aRow = tid >> 1;            // 0..127
    const int aCol = (tid & 1) * 4;       // 0 or 4
    const int bRow = tid >> 5;            // 0..7
    const int bCol = (tid & 31) * 4;      // 0..124

    const int ty = tid >> 4;              // 0..15
    const int tx = tid & 15;              // 0..15

    float acc[8][8];
    #pragma unroll
    for (int i = 0; i < 8; i++)
        #pragma unroll
        for (int j = 0; j < 8; j++) acc[i][j] = 0.0f;

    const float* Ap = A + (size_t)(row0 + aRow) * K + aCol;
    const float* Bp = Bm + col0 + bCol;

    for (int kk = 0; kk < K; kk += 8) {
        float4 av = *(const float4*)(Ap + kk);
        As[aCol + 0][aRow] = av.x;
        As[aCol + 1][aRow] = av.y;
        As[aCol + 2][aRow] = av.z;
        As[aCol + 3][aRow] = av.w;
        float4 bv = *(const float4*)(Bp + (size_t)(kk + bRow) * N);
        *(float4*)&Bs[bRow][bCol] = bv;
        __syncthreads();

        #pragma unroll
        for (int k = 0; k < 8; k++) {
            float a[8], bq[8];
            *(float4*)&a [0] = *(float4*)&As[k][ty * 8];
            *(float4*)&a [4] = *(float4*)&As[k][ty * 8 + 4];
            *(float4*)&bq[0] = *(float4*)&Bs[k][tx * 8];
            *(float4*)&bq[4] = *(float4*)&Bs[k][tx * 8 + 4];
            #pragma unroll
            for (int i = 0; i < 8; i++)
                #pragma unroll
                for (int j = 0; j < 8; j++)
                    acc[i][j] = fmaf(a[i], bq[j], acc[i][j]);
        }
        __syncthreads();
    }

    const int crow = row0 + ty * 8;
    const int ccol = col0 + tx * 8;
    #pragma unroll
    for (int i = 0; i < 8; i++) {
        #pragma unroll
        for (int j = 0; j < 8; j += 4) {
            float4 o;
            o.x = acc[i][j + 0] + bias[ccol + j + 0];
            o.y = acc[i][j + 1] + bias[ccol + j + 1];
            o.z = acc[i][j + 2] + bias[ccol + j + 2];
            o.w = acc[i][j + 3] + bias[ccol + j + 3];
            if (EPI == EPI_BIAS_GELU) {
                o.x = gelu_exact(o.x); o.y = gelu_exact(o.y);
                o.z = gelu_exact(o.z); o.w = gelu_exact(o.w);
            }
            if (EPI == EPI_BIAS_RES) {
                float4 r = *(const float4*)(Rm + (size_t)(crow + i) * N + ccol + j);
                o.x += r.x; o.y += r.y; o.z += r.z; o.w += r.w;
            }
            *(float4*)(C + (size_t)(crow + i) * N + ccol + j) = o;
        }
    }
}

// ---------------------------------------------------------------------------
// Flash-style causal attention. One CTA per (q-tile of 64, b*h).
// 256 threads: thread (tr,tc) = (tid/16, tid%16) owns 4x4 of each 64x64 tile.
// smem tiles stored transposed so both GEMM phases use LDS.128.
// ---------------------------------------------------------------------------
#define ATS 68                           // padded stride (multiple of 4)
#define ATTN_SMEM (4 * 64 * ATS * 4)     // Qts,Kts,Vs,Pts = 69632 B

__global__ __launch_bounds__(256)
void attn_kernel(const float* __restrict__ q, const float* __restrict__ k,
                 const float* __restrict__ v, float* __restrict__ z)
{
    extern __shared__ float sm[];
    float* Qts = sm;               // [m][qrow]
    float* Kts = sm + 64 * ATS;    // [m][krow]
    float* Vs  = sm + 2 * 64 * ATS;// [krow][vcol]
    float* Pts = sm + 3 * 64 * ATS;// [kcol][qrow]

    const int tid = threadIdx.x;
    const int qt  = blockIdx.x;            // 0..31
    const int bh  = blockIdx.y;            // 0..31
    const int b   = bh >> 4;
    const int h   = bh & 15;
    const int tr  = tid >> 4;
    const int tc  = tid & 15;

    // ---- load Q tile, transposed + pre-scaled by 1/sqrt(DH) ----
    #pragma unroll
    for (int it = 0; it < 4; it++) {
        int f4  = tid + it * 256;          // 0..1023
        int row = f4 >> 4;                 // 0..63
        int m   = (f4 & 15) * 4;
        int s   = qt * 64 + row;
        float4 qv = *(const float4*)(q + ((size_t)((b * SS + s) * HH + h)) * DHH + m);
        Qts[(m + 0) * ATS + row] = qv.x * 0.125f;
        Qts[(m + 1) * ATS + row] = qv.y * 0.125f;
        Qts[(m + 2) * ATS + row] = qv.z * 0.125f;
        Qts[(m + 3) * ATS + row] = qv.w * 0.125f;
    }

    float o[4][4];
    float mold[4], l[4];
    #pragma unroll
    for (int i = 0; i < 4; i++) {
        mold[i] = -INFINITY; l[i] = 0.0f;
        #pragma unroll
        for (int j = 0; j < 4; j++) o[i][j] = 0.0f;
    }
    __syncthreads();

    for (int kt = 0; kt <= qt; kt++) {
        // ---- load K (transposed) and V tiles ----
        #pragma unroll
        for (int it = 0; it < 4; it++) {
            int f4  = tid + it * 256;
            int row = f4 >> 4;
            int m   = (f4 & 15) * 4;
            int s   = kt * 64 + row;
            size_t base = ((size_t)((b * SS + s) * HH + h)) * DHH + m;
            float4 kv = *(const float4*)(k + base);
            Kts[(m + 0) * ATS + row] = kv.x;
            Kts[(m + 1) * ATS + row] = kv.y;
            Kts[(m + 2) * ATS + row] = kv.z;
            Kts[(m + 3) * ATS + row] = kv.w;
            float4 vv = *(const float4*)(v + base);
            *(float4*)&Vs[row * ATS + m] = vv;
        }
        __syncthreads();

        // ---- phase 1: S = Q @ K^T ----
        float s4[4][4];
        #pragma unroll
        for (int i = 0; i < 4; i++)
            #pragma unroll
            for (int j = 0; j < 4; j++) s4[i][j] = 0.0f;

        #pragma unroll 8
        for (int m = 0; m < 64; m++) {
            float4 qa = *(float4*)&Qts[m * ATS + tr * 4];
            float4 kb = *(float4*)&Kts[m * ATS + tc * 4];
            float aa[4] = {qa.x, qa.y, qa.z, qa.w};
            float bb[4] = {kb.x, kb.y, kb.z, kb.w};
            #pragma unroll
            for (int i = 0; i < 4; i++)
                #pragma unroll
                for (int j = 0; j < 4; j++)
                    s4[i][j] = fmaf(aa[i], bb[j], s4[i][j]);
        }

        // ---- causal mask (diagonal tile only) ----
        if (kt == qt) {
            #pragma unroll
            for (int i = 0; i < 4; i++) {
                int qg = tr * 4 + i;
                #pragma unroll
                for (int j = 0; j < 4; j++) {
                    int kg = tc * 4 + j;
                    if (kg > qg) s4[i][j] = -1e30f;
                }
            }
        }

        // ---- online softmax update ----
        #pragma unroll
        for (int i = 0; i < 4; i++) {
            float mx = fmaxf(fmaxf(s4[i][0], s4[i][1]), fmaxf(s4[i][2], s4[i][3]));
            #pragma unroll
            for (int off = 8; off > 0; off >>= 1)
                mx = fmaxf(mx, __shfl_xor_sync(0xffffffffu, mx, off, 16));
            float mnew = fmaxf(mold[i], mx);
            float fac  = expf(mold[i] - mnew);
            float rs = 0.0f;
            #pragma unroll
            for (int j = 0; j < 4; j++) {
                s4[i][j] = expf(s4[i][j] - mnew);
                rs += s4[i][j];
            }
            #pragma unroll
            for (int off = 8; off > 0; off >>= 1)
                rs += __shfl_xor_sync(0xffffffffu, rs, off, 16);
            l[i]    = l[i] * fac + rs;
            mold[i] = mnew;
            #pragma unroll
            for (int j = 0; j < 4; j++) o[i][j] *= fac;
        }

        // ---- write P transposed ----
        #pragma unroll
        for (int i = 0; i < 4; i++)
            #pragma unroll
            for (int j = 0; j < 4; j++)
                Pts[(tc * 4 + j) * ATS + tr * 4 + i] = s4[i][j];
        __syncthreads();

        // ---- phase 2: O += P @ V ----
        #pragma unroll 8
        for (int kk = 0; kk < 64; kk++) {
            float4 pa = *(float4*)&Pts[kk * ATS + tr * 4];
            float4 vb = *(float4*)&Vs [kk * ATS + tc * 4];
            float aa[4] = {pa.x, pa.y, pa.z, pa.w};
            float bb[4] = {vb.x, vb.y, vb.z, vb.w};
            #pragma unroll
            for (int i = 0; i < 4; i++)
                #pragma unroll
                for (int j = 0; j < 4; j++)
                    o[i][j] = fmaf(aa[i], bb[j], o[i][j]);
        }
        __syncthreads();
    }

    // ---- finalize + store z[b,q,h,dh] ----
    #pragma unroll
    for (int i = 0; i < 4; i++) {
        float invl = 1.0f / l[i];
        int s = qt * 64 + tr * 4 + i;
        float4 o4;
        o4.x = o[i][0] * invl; o4.y = o[i][1] * invl;
        o4.z = o[i][2] * invl; o4.w = o[i][3] * invl;
        *(float4*)(z + ((size_t)((b * SS + s) * HH + h)) * DHH + tc * 4) = o4;
    }
}

// ---------------------------------------------------------------------------
// Host launcher
// ---------------------------------------------------------------------------
extern "C" void kernel_launch(void* const* d_in, const int* in_sizes, int n_in,
                              void* d_out, int out_size)
{
    (void)in_sizes; (void)n_in; (void)out_size;
    const float* resid = (const float*)d_in[0];
    const float* ln1w  = (const float*)d_in[1];
    const float* ln1b  = (const float*)d_in[2];
    const float* WQ    = (const float*)d_in[3];
    const float* bQ    = (const float*)d_in[4];
    const float* WK    = (const float*)d_in[5];
    const float* bK    = (const float*)d_in[6];
    const float* WV    = (const float*)d_in[7];
    const float* bV    = (const float*)d_in[8];
    const float* WO    = (const float*)d_in[9];
    const float* bO    = (const float*)d_in[10];
    const float* ln2w  = (const float*)d_in[11];
    const float* ln2b  = (const float*)d_in[12];
    const float* Win   = (const float*)d_in[13];
    const float* bin   = (const float*)d_in[14];
    const float* Wout  = (const float*)d_in[15];
    const float* bout  = (const float*)d_in[16];

    float *xn, *q, *k, *v, *z, *mid, *act, *wt;
    cudaGetSymbolAddress((void**)&xn,  g_xn);
    cudaGetSymbolAddress((void**)&q,   g_q);
    cudaGetSymbolAddress((void**)&k,   g_k);
    cudaGetSymbolAddress((void**)&v,   g_v);
    cudaGetSymbolAddress((void**)&z,   g_z);
    cudaGetSymbolAddress((void**)&mid, g_mid);
    cudaGetSymbolAddress((void**)&act, g_act);
    cudaGetSymbolAddress((void**)&wt,  g_wt);

    cudaFuncSetAttribute(attn_kernel, cudaFuncAttributeMaxDynamicSharedMemorySize,
                         ATTN_SMEM);

    // 1) LN1
    ln_kernel<<<NTOK, 256>>>(resid, ln1w, ln1b, xn);

    // 2) QKV projections (transpose weight, then GEMM + bias)
    dim3 g1024(DD / 128, NTOK / 128);   // N=1024
    qkvw_transpose<<<1024, 256>>>(WQ, wt);
    sgemm_kernel<EPI_BIAS><<<g1024, 256>>>(xn, wt, bQ, nullptr, q, NTOK, DD, DD);
    qkvw_transpose<<<1024, 256>>>(WK, wt);
    sgemm_kernel<EPI_BIAS><<<g1024, 256>>>(xn, wt, bK, nullptr, k, NTOK, DD, DD);
    qkvw_transpose<<<1024, 256>>>(WV, wt);
    sgemm_kernel<EPI_BIAS><<<g1024, 256>>>(xn, wt, bV, nullptr, v, NTOK, DD, DD);

    // 3) causal attention -> z[b,q,h,dh]
    dim3 ga(SS / 64, BB * HH);
    attn_kernel<<<ga, 256, ATTN_SMEM>>>(q, k, v, z);

    // 4) output projection + residual -> resid_mid
    sgemm_kernel<EPI_BIAS_RES><<<g1024, 256>>>(z, WO, bO, resid, mid, NTOK, DD, DD);

    // 5) LN2
    ln_kernel<<<NTOK, 256>>>(mid, ln2w, ln2b, xn);

    // 6) MLP in + exact GELU
    dim3 g4096(DMM / 128, NTOK / 128);
    sgemm_kernel<EPI_BIAS_GELU><<<g4096, 256>>>(xn, Win, bin, nullptr, act,
                                                NTOK, DMM, DD);

    // 7) MLP out + bias + residual -> d_out
    sgemm_kernel<EPI_BIAS_RES><<<g1024, 256>>>(act, Wout, bout, mid,
                                               (float*)d_out, NTOK, DD, DMM);
}

// round 3
// speedup vs baseline: 1.8465x; 1.8465x over previous
#include <cuda_runtime.h>
#include <cuda_bf16.h>
#include <math.h>
#include <stdint.h>

// Problem constants
#define BB   2
#define SS   2048
#define DD   1024
#define HH   16
#define DHH  64
#define DMM  4096
#define NTOK (BB*SS)          // 4096
#define EPSLN 1e-5f

typedef __nv_bfloat16  bf16;
typedef __nv_bfloat162 bf162;

// ---------------------------------------------------------------------------
// Device scratch (allocation-free rule: __device__ globals)
// ---------------------------------------------------------------------------
__device__ float g_q  [NTOK*DD];
__device__ float g_k  [NTOK*DD];
__device__ float g_v  [NTOK*DD];
__device__ float g_z  [NTOK*DD];
__device__ float g_mid[NTOK*DD];
__device__ bf16  g_xh [NTOK*DD];     // split activations (hi)
__device__ bf16  g_xl [NTOK*DD];     // split activations (lo)
__device__ bf16  g_acth[NTOK*DMM];   // gelu output split (hi)
__device__ bf16  g_actl[NTOK*DMM];   // gelu output split (lo)
__device__ bf16  g_wh [DD*DMM];      // split transposed weight (hi) - reused
__device__ bf16  g_wl [DD*DMM];      // split transposed weight (lo) - reused

// ---------------------------------------------------------------------------
// Helpers
// ---------------------------------------------------------------------------
__device__ __forceinline__ void split2(float x, bf16& h, bf16& l)
{
    h = __float2bfloat16_rn(x);
    l = __float2bfloat16_rn(x - __bfloat162float(h));
}

__device__ __forceinline__ uint32_t cvta_s(const void* p)
{
    return (uint32_t)__cvta_generic_to_shared(p);
}

__device__ __forceinline__ void cp16(uint32_t s, const void* g)
{
    asm volatile("cp.async.cg.shared.global [%0], [%1], 16;" :: "r"(s), "l"(g));
}

__device__ __forceinline__ void ldsm4(unsigned r[4], uint32_t a)
{
    asm volatile("ldmatrix.sync.aligned.m8n8.x4.shared.b16 {%0,%1,%2,%3}, [%4];"
                 : "=r"(r[0]), "=r"(r[1]), "=r"(r[2]), "=r"(r[3]) : "r"(a));
}

__device__ __forceinline__ void mma16816(float c[4], const unsigned a[4],
                                         const unsigned b[2])
{
    asm volatile(
        "mma.sync.aligned.m16n8k16.row.col.f32.bf16.bf16.f32 "
        "{%0,%1,%2,%3}, {%4,%5,%6,%7}, {%8,%9}, {%0,%1,%2,%3};"
        : "+f"(c[0]), "+f"(c[1]), "+f"(c[2]), "+f"(c[3])
        : "r"(a[0]), "r"(a[1]), "r"(a[2]), "r"(a[3]), "r"(b[0]), "r"(b[1]));
}

__device__ __forceinline__ float gelu_exact(float x)
{
    return 0.5f * x * (1.0f + erff(x * 0.70710678118654752f));
}

// ---------------------------------------------------------------------------
// LayerNorm + split to bf16 hi/lo. One block per row, 256 threads.
// ---------------------------------------------------------------------------
__global__ __launch_bounds__(256)
void ln_split_kernel(const float* __restrict__ x, const float* __restrict__ w,
                     const float* __restrict__ b, bf16* __restrict__ oh,
                     bf16* __restrict__ ol)
{
    __shared__ float red[8];
    __shared__ float bcast;
    const int row = blockIdx.x;
    const int tid = threadIdx.x;
    const int lane = tid & 31, warp = tid >> 5;

    float4 v = ((const float4*)(x + (size_t)row * DD))[tid];

    float s = v.x + v.y + v.z + v.w;
    #pragma unroll
    for (int o = 16; o > 0; o >>= 1) s += __shfl_xor_sync(0xffffffffu, s, o);
    if (lane == 0) red[warp] = s;
    __syncthreads();
    if (tid < 8) {
        float t = red[tid];
        #pragma unroll
        for (int o = 4; o > 0; o >>= 1) t += __shfl_xor_sync(0xffu, t, o);
        if (tid == 0) bcast = t;
    }
    __syncthreads();
    const float mean = bcast * (1.0f / DD);
    __syncthreads();

    float dx0 = v.x - mean, dx1 = v.y - mean, dx2 = v.z - mean, dx3 = v.w - mean;
    float sq = dx0*dx0 + dx1*dx1 + dx2*dx2 + dx3*dx3;
    #pragma unroll
    for (int o = 16; o > 0; o >>= 1) sq += __shfl_xor_sync(0xffffffffu, sq, o);
    if (lane == 0) red[warp] = sq;
    __syncthreads();
    if (tid < 8) {
        float t = red[tid];
        #pragma unroll
        for (int o = 4; o > 0; o >>= 1) t += __shfl_xor_sync(0xffu, t, o);
        if (tid == 0) bcast = t;
    }
    __syncthreads();
    const float inv = rsqrtf(bcast * (1.0f / DD) + EPSLN);

    float4 wv = ((const float4*)w)[tid];
    float4 bv = ((const float4*)b)[tid];
    float o0 = dx0 * inv * wv.x + bv.x;
    float o1 = dx1 * inv * wv.y + bv.y;
    float o2 = dx2 * inv * wv.z + bv.z;
    float o3 = dx3 * inv * wv.w + bv.w;

    bf16 h0,h1,h2,h3,l0,l1,l2,l3;
    split2(o0,h0,l0); split2(o1,h1,l1); split2(o2,h2,l2); split2(o3,h3,l3);
    bf162* H = (bf162*)(oh + (size_t)row * DD + tid * 4);
    bf162* L = (bf162*)(ol + (size_t)row * DD + tid * 4);
    bf162 t0; t0.x = h0; t0.y = h1; H[0] = t0;
    bf162 t1; t1.x = h2; t1.y = h3; H[1] = t1;
    bf162 t2; t2.x = l0; t2.y = l1; L[0] = t2;
    bf162 t3; t3.x = l2; t3.y = l3; L[1] = t3;
}

// ---------------------------------------------------------------------------
// Elementwise split: fp32 -> (hi, lo) bf16. One float4 per thread.
// ---------------------------------------------------------------------------
__global__ __launch_bounds__(256)
void split_kernel(const float* __restrict__ x, bf16* __restrict__ oh,
                  bf16* __restrict__ ol)
{
    int i = blockIdx.x * blockDim.x + threadIdx.x;
    float4 v = ((const float4*)x)[i];
    bf16 h0,h1,h2,h3,l0,l1,l2,l3;
    split2(v.x,h0,l0); split2(v.y,h1,l1); split2(v.z,h2,l2); split2(v.w,h3,l3);
    bf162* H = (bf162*)(oh + (size_t)i * 4);
    bf162* L = (bf162*)(ol + (size_t)i * 4);
    bf162 t0; t0.x = h0; t0.y = h1; H[0] = t0;
    bf162 t1; t1.x = h2; t1.y = h3; H[1] = t1;
    bf162 t2; t2.x = l0; t2.y = l1; L[0] = t2;
    bf162 t3; t3.x = l2; t3.y = l3; L[1] = t3;
}

// ---------------------------------------------------------------------------
// Transpose + split: in fp32 matrix z of shape [R][C] at in + z*R*C.
// Writes out[(z*C + c)*R + r] = split(in[z][r][c])   (K-major B layout)
// block (32, 8); grid (C/32, R/32, Z)
// ---------------------------------------------------------------------------
__global__ __launch_bounds__(256)
void tsplit_kernel(const float* __restrict__ in, bf16* __restrict__ oh,
                   bf16* __restrict__ ol, int R, int C)
{
    __shared__ float t[32][33];
    const int tx = threadIdx.x, ty = threadIdx.y;
    const int c0 = blockIdx.x * 32, r0 = blockIdx.y * 32, z = blockIdx.z;
    const float* src = in + (size_t)z * R * C;
    #pragma unroll
    for (int i = 0; i < 4; i++)
        t[ty + 8*i][tx] = src[(size_t)(r0 + ty + 8*i) * C + c0 + tx];
    __syncthreads();
    #pragma unroll
    for (int i = 0; i < 4; i++) {
        int c = c0 + ty + 8*i;
        float v = t[tx][ty + 8*i];
        size_t o = (size_t)(z * C + c) * R + r0 + tx;
        bf16 h, l; split2(v, h, l);
        oh[o] = h; ol[o] = l;
    }
}

// ---------------------------------------------------------------------------
// Split-bf16 tensor-core GEMM: C[M,N] = A[M,K] @ B[K,N]
// A given as hi/lo bf16 row-major [M][K]; B as hi/lo bf16 [N][K] (transposed).
// C = Ah*Bh + Al*Bh + Ah*Bl (fp32 accum). BM=BN=128, BK=32, 256 thr,
// warp tile 32x64 (4 warps M x 2 warps N), 2-stage cp.async pipeline.
// EPI: 0 = bias -> Cf    1 = bias+gelu -> split(Oh,Ol)    2 = bias+res -> Cf
// ---------------------------------------------------------------------------
#define EPI_BIAS       0
#define EPI_BIAS_GELU  1
#define EPI_BIAS_RES   2

#define ASTR 40                    // padded smem row stride (bf16 elems), 80B
#define TSZ  (128*ASTR)            // elems per tile
#define STG  (4*TSZ)               // elems per stage (Ah,Al,Bh,Bl)

template <int EPI>
__global__ __launch_bounds__(256, 2)
void gemm_bf16(const bf16* __restrict__ Ah, const bf16* __restrict__ Al,
               const bf16* __restrict__ Bh, const bf16* __restrict__ Bl,
               const float* __restrict__ bias, const float* __restrict__ Rm,
               float* __restrict__ Cf, bf16* __restrict__ Oh,
               bf16* __restrict__ Ol, int M, int N, int K)
{
    extern __shared__ bf16 sm[];
    const int tid = threadIdx.x;
    const int bx = blockIdx.x, by = blockIdx.y;
    const int warp = tid >> 5, lane = tid & 31;
    const int wm = warp >> 1, wn = warp & 1;

    // ---- global->smem copy indexing (each thread: one 32B span per tile) ----
    const int lrow = tid >> 1;
    const int lcol = (tid & 1) * 16;
    const bf16* gAh = Ah + (size_t)(by * 128 + lrow) * K + lcol;
    const bf16* gAl = Al + (size_t)(by * 128 + lrow) * K + lcol;
    const bf16* gBh = Bh + (size_t)(bx * 128 + lrow) * K + lcol;
    const bf16* gBl = Bl + (size_t)(bx * 128 + lrow) * K + lcol;
    const uint32_t sbase = cvta_s(sm);
    const uint32_t soff = (lrow * ASTR + lcol) * 2;   // bytes (80B stride: 16B aligned)

    float acc[2][8][4];
    #pragma unroll
    for (int i = 0; i < 2; i++)
        #pragma unroll
        for (int j = 0; j < 8; j++)
            #pragma unroll
            for (int q = 0; q < 4; q++) acc[i][j][q] = 0.0f;

    // ldmatrix lane decodes
    const int a_r = (lane & 7) + ((lane >> 3) & 1) * 8;
    const int a_c = (lane >> 4) * 8;
    const int b_r = (lane & 7) + (lane >> 4) * 8;
    const int b_c = ((lane >> 3) & 1) * 8;

    const int T = K / 32;

    // stage byte bases
    auto issue = [&](int s, int kk) {
        uint32_t st = sbase + (uint32_t)s * STG * 2;
        cp16(st + soff,             gAh + kk);
        cp16(st + soff + 16,        gAh + kk + 8);
        cp16(st + TSZ*2 + soff,     gAl + kk);
        cp16(st + TSZ*2 + soff + 16,gAl + kk + 8);
        cp16(st + TSZ*4 + soff,     gBh + kk);
        cp16(st + TSZ*4 + soff + 16,gBh + kk + 8);
        cp16(st + TSZ*6 + soff,     gBl + kk);
        cp16(st + TSZ*6 + soff + 16,gBl + kk + 8);
        asm volatile("cp.async.commit_group;");
    };

    issue(0, 0);

    for (int t = 0; t < T; t++) {
        if (t + 1 < T) {
            issue((t + 1) & 1, (t + 1) * 32);
            asm volatile("cp.async.wait_group 1;");
        } else {
            asm volatile("cp.async.wait_group 0;");
        }
        __syncthreads();

        const uint32_t st = sbase + (uint32_t)(t & 1) * STG * 2;
        const uint32_t sAh = st;
        const uint32_t sAl = st + TSZ * 2;
        const uint32_t sBh = st + TSZ * 4;
        const uint32_t sBl = st + TSZ * 6;

        #pragma unroll
        for (int kc = 0; kc < 2; kc++) {
            unsigned ah[2][4], al[2][4];
            #pragma unroll
            for (int mf = 0; mf < 2; mf++) {
                uint32_t ao = ((wm*32 + mf*16 + a_r) * ASTR + kc*16 + a_c) * 2;
                ldsm4(ah[mf], sAh + ao);
                ldsm4(al[mf], sAl + ao);
            }
            #pragma unroll
            for (int p = 0; p < 4; p++) {
                unsigned bh4[4], bl4[4];
                uint32_t bo = ((wn*64 + p*16 + b_r) * ASTR + kc*16 + b_c) * 2;
                ldsm4(bh4, sBh + bo);
                ldsm4(bl4, sBl + bo);
                #pragma unroll
                for (int mf = 0; mf < 2; mf++) {
                    mma16816(acc[mf][2*p],     ah[mf], bh4);
                    mma16816(acc[mf][2*p + 1], ah[mf], bh4 + 2);
                    mma16816(acc[mf][2*p],     al[mf], bh4);
                    mma16816(acc[mf][2*p + 1], al[mf], bh4 + 2);
                    mma16816(acc[mf][2*p],     ah[mf], bl4);
                    mma16816(acc[mf][2*p + 1], ah[mf], bl4 + 2);
                }
            }
        }
        __syncthreads();
    }

    // ---- epilogue ----
    const int er = by * 128 + wm * 32 + (lane >> 2);
    const int ec = bx * 128 + wn * 64 + (lane & 3) * 2;
    #pragma unroll
    for (int mf = 0; mf < 2; mf++) {
        #pragma unroll
        for (int nf = 0; nf < 8; nf++) {
            int c = ec + nf * 8;
            float b0 = bias[c], b1 = bias[c + 1];
            #pragma unroll
            for (int half = 0; half < 2; half++) {
                int r = er + mf * 16 + half * 8;
                float v0 = acc[mf][nf][half * 2 + 0] + b0;
                float v1 = acc[mf][nf][half * 2 + 1] + b1;
                if (EPI == EPI_BIAS_GELU) {
                    v0 = gelu_exact(v0); v1 = gelu_exact(v1);
                    bf16 h0,h1,l0,l1;
                    split2(v0,h0,l0); split2(v1,h1,l1);
                    bf162 th; th.x = h0; th.y = h1;
                    bf162 tl; tl.x = l0; tl.y = l1;
                    *(bf162*)(Oh + (size_t)r * N + c) = th;
                    *(bf162*)(Ol + (size_t)r * N + c) = tl;
                } else {
                    if (EPI == EPI_BIAS_RES) {
                        float2 rr = *(const float2*)(Rm + (size_t)r * N + c);
                        v0 += rr.x; v1 += rr.y;
                    }
                    float2 o; o.x = v0; o.y = v1;
                    *(float2*)(Cf + (size_t)r * N + c) = o;
                }
            }
        }
    }
}

// ---------------------------------------------------------------------------
// Flash-style causal attention (fp32). One CTA per (q-tile of 64, b*h).
// ---------------------------------------------------------------------------
#define ATS 68
#define ATTN_SMEM (4 * 64 * ATS * 4)

__global__ __launch_bounds__(256)
void attn_kernel(const float* __restrict__ q, const float* __restrict__ k,
                 const float* __restrict__ v, float* __restrict__ z)
{
    extern __shared__ float smf[];
    float* Qts = smf;
    float* Kts = smf + 64 * ATS;
    float* Vs  = smf + 2 * 64 * ATS;
    float* Pts = smf + 3 * 64 * ATS;

    const int tid = threadIdx.x;
    const int qt  = blockIdx.x;
    const int bh  = blockIdx.y;
    const int b   = bh >> 4;
    const int h   = bh & 15;
    const int tr  = tid >> 4;
    const int tc  = tid & 15;

    #pragma unroll
    for (int it = 0; it < 4; it++) {
        int f4  = tid + it * 256;
        int row = f4 >> 4;
        int m   = (f4 & 15) * 4;
        int s   = qt * 64 + row;
        float4 qv = *(const float4*)(q + ((size_t)((b * SS + s) * HH + h)) * DHH + m);
        Qts[(m + 0) * ATS + row] = qv.x * 0.125f;
        Qts[(m + 1) * ATS + row] = qv.y * 0.125f;
        Qts[(m + 2) * ATS + row] = qv.z * 0.125f;
        Qts[(m + 3) * ATS + row] = qv.w * 0.125f;
    }

    float o[4][4];
    float mold[4], l[4];
    #pragma unroll
    for (int i = 0; i < 4; i++) {
        mold[i] = -INFINITY; l[i] = 0.0f;
        #pragma unroll
        for (int j = 0; j < 4; j++) o[i][j] = 0.0f;
    }
    __syncthreads();

    for (int kt = 0; kt <= qt; kt++) {
        #pragma unroll
        for (int it = 0; it < 4; it++) {
            int f4  = tid + it * 256;
            int row = f4 >> 4;
            int m   = (f4 & 15) * 4;
            int s   = kt * 64 + row;
            size_t base = ((size_t)((b * SS + s) * HH + h)) * DHH + m;
            float4 kv = *(const float4*)(k + base);
            Kts[(m + 0) * ATS + row] = kv.x;
            Kts[(m + 1) * ATS + row] = kv.y;
            Kts[(m + 2) * ATS + row] = kv.z;
            Kts[(m + 3) * ATS + row] = kv.w;
            float4 vv = *(const float4*)(v + base);
            *(float4*)&Vs[row * ATS + m] = vv;
        }
        __syncthreads();

        float s4[4][4];
        #pragma unroll
        for (int i = 0; i < 4; i++)
            #pragma unroll
            for (int j = 0; j < 4; j++) s4[i][j] = 0.0f;

        #pragma unroll 8
        for (int m = 0; m < 64; m++) {
            float4 qa = *(float4*)&Qts[m * ATS + tr * 4];
            float4 kb = *(float4*)&Kts[m * ATS + tc * 4];
            float aa[4] = {qa.x, qa.y, qa.z, qa.w};
            float bb[4] = {kb.x, kb.y, kb.z, kb.w};
            #pragma unroll
            for (int i = 0; i < 4; i++)
                #pragma unroll
                for (int j = 0; j < 4; j++)
                    s4[i][j] = fmaf(aa[i], bb[j], s4[i][j]);
        }

        if (kt == qt) {
            #pragma unroll
            for (int i = 0; i < 4; i++) {
                int qg = tr * 4 + i;
                #pragma unroll
                for (int j = 0; j < 4; j++) {
                    int kg = tc * 4 + j;
                    if (kg > qg) s4[i][j] = -1e30f;
                }
            }
        }

        #pragma unroll
        for (int i = 0; i < 4; i++) {
            float mx = fmaxf(fmaxf(s4[i][0], s4[i][1]), fmaxf(s4[i][2], s4[i][3]));
            #pragma unroll
            for (int off = 8; off > 0; off >>= 1)
                mx = fmaxf(mx, __shfl_xor_sync(0xffffffffu, mx, off, 16));
            float mnew = fmaxf(mold[i], mx);
            float fac  = expf(mold[i] - mnew);
            float rs = 0.0f;
            #pragma unroll
            for (int j = 0; j < 4; j++) {
                s4[i][j] = expf(s4[i][j] - mnew);
                rs += s4[i][j];
            }
            #pragma unroll
            for (int off = 8; off > 0; off >>= 1)
                rs += __shfl_xor_sync(0xffffffffu, rs, off, 16);
            l[i]    = l[i] * fac + rs;
            mold[i] = mnew;
            #pragma unroll
            for (int j = 0; j < 4; j++) o[i][j] *= fac;
        }

        #pragma unroll
        for (int i = 0; i < 4; i++)
            #pragma unroll
            for (int j = 0; j < 4; j++)
                Pts[(tc * 4 + j) * ATS + tr * 4 + i] = s4[i][j];
        __syncthreads();

        #pragma unroll 8
        for (int kk = 0; kk < 64; kk++) {
            float4 pa = *(float4*)&Pts[kk * ATS + tr * 4];
            float4 vb = *(float4*)&Vs [kk * ATS + tc * 4];
            float aa[4] = {pa.x, pa.y, pa.z, pa.w};
            float bb[4] = {vb.x, vb.y, vb.z, vb.w};
            #pragma unroll
            for (int i = 0; i < 4; i++)
                #pragma unroll
                for (int j = 0; j < 4; j++)
                    o[i][j] = fmaf(aa[i], bb[j], o[i][j]);
        }
        __syncthreads();
    }

    #pragma unroll
    for (int i = 0; i < 4; i++) {
        float invl = 1.0f / l[i];
        int s = qt * 64 + tr * 4 + i;
        float4 o4;
        o4.x = o[i][0] * invl; o4.y = o[i][1] * invl;
        o4.z = o[i][2] * invl; o4.w = o[i][3] * invl;
        *(float4*)(z + ((size_t)((b * SS + s) * HH + h)) * DHH + tc * 4) = o4;
    }
}

// ---------------------------------------------------------------------------
// Host launcher
// ---------------------------------------------------------------------------
#define GEMM_SMEM (2 * STG * 2)   // bytes: 2 stages * 4 tiles * 128*40 bf16

extern "C" void kernel_launch(void* const* d_in, const int* in_sizes, int n_in,
                              void* d_out, int out_size)
{
    (void)in_sizes; (void)n_in; (void)out_size;
    const float* resid = (const float*)d_in[0];
    const float* ln1w  = (const float*)d_in[1];
    const float* ln1b  = (const float*)d_in[2];
    const float* WQ    = (const float*)d_in[3];
    const float* bQ    = (const float*)d_in[4];
    const float* WK    = (const float*)d_in[5];
    const float* bK    = (const float*)d_in[6];
    const float* WV    = (const float*)d_in[7];
    const float* bV    = (const float*)d_in[8];
    const float* WO    = (const float*)d_in[9];
    const float* bO    = (const float*)d_in[10];
    const float* ln2w  = (const float*)d_in[11];
    const float* ln2b  = (const float*)d_in[12];
    const float* Win   = (const float*)d_in[13];
    const float* bin   = (const float*)d_in[14];
    const float* Wout  = (const float*)d_in[15];
    const float* bout  = (const float*)d_in[16];

    float *q, *k, *v, *z, *mid;
    bf16 *xh, *xl, *acth, *actl, *wh, *wl;
    cudaGetSymbolAddress((void**)&q,    g_q);
    cudaGetSymbolAddress((void**)&k,    g_k);
    cudaGetSymbolAddress((void**)&v,    g_v);
    cudaGetSymbolAddress((void**)&z,    g_z);
    cudaGetSymbolAddress((void**)&mid,  g_mid);
    cudaGetSymbolAddress((void**)&xh,   g_xh);
    cudaGetSymbolAddress((void**)&xl,   g_xl);
    cudaGetSymbolAddress((void**)&acth, g_acth);
    cudaGetSymbolAddress((void**)&actl, g_actl);
    cudaGetSymbolAddress((void**)&wh,   g_wh);
    cudaGetSymbolAddress((void**)&wl,   g_wl);

    cudaFuncSetAttribute(attn_kernel, cudaFuncAttributeMaxDynamicSharedMemorySize,
                         ATTN_SMEM);
    cudaFuncSetAttribute(gemm_bf16<EPI_BIAS>,
                         cudaFuncAttributeMaxDynamicSharedMemorySize, GEMM_SMEM);
    cudaFuncSetAttribute(gemm_bf16<EPI_BIAS_GELU>,
                         cudaFuncAttributeMaxDynamicSharedMemorySize, GEMM_SMEM);
    cudaFuncSetAttribute(gemm_bf16<EPI_BIAS_RES>,
                         cudaFuncAttributeMaxDynamicSharedMemorySize, GEMM_SMEM);

    dim3 tb(32, 8);
    dim3 g1024(DD / 128, NTOK / 128);    // N=1024 gemms
    dim3 g4096(DMM / 128, NTOK / 128);   // N=4096 gemm

    // 1) LN1 -> split
    ln_split_kernel<<<NTOK, 256>>>(resid, ln1w, ln1b, xh, xl);

    // 2) QKV projections
    tsplit_kernel<<<dim3(DHH/32, DD/32, HH), tb>>>(WQ, wh, wl, DD, DHH);
    gemm_bf16<EPI_BIAS><<<g1024, 256, GEMM_SMEM>>>(xh, xl, wh, wl, bQ, nullptr,
                                                   q, nullptr, nullptr,
                                                   NTOK, DD, DD);
    tsplit_kernel<<<dim3(DHH/32, DD/32, HH), tb>>>(WK, wh, wl, DD, DHH);
    gemm_bf16<EPI_BIAS><<<g1024, 256, GEMM_SMEM>>>(xh, xl, wh, wl, bK, nullptr,
                                                   k, nullptr, nullptr,
                                                   NTOK, DD, DD);
    tsplit_kernel<<<dim3(DHH/32, DD/32, HH), tb>>>(WV, wh, wl, DD, DHH);
    gemm_bf16<EPI_BIAS><<<g1024, 256, GEMM_SMEM>>>(xh, xl, wh, wl, bV, nullptr,
                                                   v, nullptr, nullptr,
                                                   NTOK, DD, DD);

    // 3) causal attention -> z
    dim3 ga(SS / 64, BB * HH);
    attn_kernel<<<ga, 256, ATTN_SMEM>>>(q, k, v, z);

    // 4) O-projection + residual -> mid
    split_kernel<<<NTOK * DD / 4 / 256, 256>>>(z, xh, xl);
    tsplit_kernel<<<dim3(DD/32, DD/32, 1), tb>>>(WO, wh, wl, DD, DD);
    gemm_bf16<EPI_BIAS_RES><<<g1024, 256, GEMM_SMEM>>>(xh, xl, wh, wl, bO, resid,
                                                       mid, nullptr, nullptr,
                                                       NTOK, DD, DD);

    // 5) LN2 -> split
    ln_split_kernel<<<NTOK, 256>>>(mid, ln2w, ln2b, xh, xl);

    // 6) MLP in + exact GELU -> split act
    tsplit_kernel<<<dim3(DMM/32, DD/32, 1), tb>>>(Win, wh, wl, DD, DMM);
    gemm_bf16<EPI_BIAS_GELU><<<g4096, 256, GEMM_SMEM>>>(xh, xl, wh, wl, bin,
                                                        nullptr, nullptr,
                                                        acth, actl,
                                                        NTOK, DMM, DD);

    // 7) MLP out + bias + residual -> d_out
    tsplit_kernel<<<dim3(DD/32, DMM/32, 1), tb>>>(Wout, wh, wl, DMM, DD);
    gemm_bf16<EPI_BIAS_RES><<<g1024, 256, GEMM_SMEM>>>(acth, actl, wh, wl, bout,
                                                       mid, (float*)d_out,
                                                       nullptr, nullptr,
                                                       NTOK, DD, DMM);
}

// round 7
// speedup vs baseline: 2.4855x; 1.3461x over previous
#include <cuda_runtime.h>
#include <cuda_bf16.h>
#include <math.h>
#include <stdint.h>

// Problem constants
#define BB   2
#define SS   2048
#define DD   1024
#define HH   16
#define DHH  64
#define DMM  4096
#define NTOK (BB*SS)          // 4096
#define EPSLN 1e-5f

typedef __nv_bfloat16  bf16;
typedef __nv_bfloat162 bf162;

// ---------------------------------------------------------------------------
// Device scratch
// ---------------------------------------------------------------------------
__device__ float g_mid[NTOK*DD];
__device__ float g_bias[3*DD];        // concatenated QKV bias
__device__ bf16  g_xh [NTOK*DD];      // split activations (hi)
__device__ bf16  g_xl [NTOK*DD];      // split activations (lo)
__device__ bf16  g_qkvh[NTOK*3*DD];   // fused QKV output (hi)
__device__ bf16  g_qkvl[NTOK*3*DD];   // fused QKV output (lo)
__device__ bf16  g_acth[NTOK*DMM];    // gelu output split (hi)
__device__ bf16  g_actl[NTOK*DMM];    // gelu output split (lo)
__device__ bf16  g_wh [DD*DMM];       // split transposed weight (hi) - reused
__device__ bf16  g_wl [DD*DMM];       // split transposed weight (lo) - reused

// ---------------------------------------------------------------------------
// Helpers
// ---------------------------------------------------------------------------
__device__ __forceinline__ void split2(float x, bf16& h, bf16& l)
{
    h = __float2bfloat16_rn(x);
    l = __float2bfloat16_rn(x - __bfloat162float(h));
}

__device__ __forceinline__ uint32_t cvta_s(const void* p)
{
    return (uint32_t)__cvta_generic_to_shared(p);
}

__device__ __forceinline__ void cp16(uint32_t s, const void* g)
{
    asm volatile("cp.async.cg.shared.global [%0], [%1], 16;" :: "r"(s), "l"(g));
}

__device__ __forceinline__ void ldsm4(unsigned r[4], uint32_t a)
{
    asm volatile("ldmatrix.sync.aligned.m8n8.x4.shared.b16 {%0,%1,%2,%3}, [%4];"
                 : "=r"(r[0]), "=r"(r[1]), "=r"(r[2]), "=r"(r[3]) : "r"(a));
}

__device__ __forceinline__ void ldsm4t(unsigned r[4], uint32_t a)
{
    asm volatile("ldmatrix.sync.aligned.m8n8.x4.trans.shared.b16 {%0,%1,%2,%3}, [%4];"
                 : "=r"(r[0]), "=r"(r[1]), "=r"(r[2]), "=r"(r[3]) : "r"(a));
}

__device__ __forceinline__ void mma16816(float c[4], const unsigned a[4],
                                         const unsigned b[2])
{
    asm volatile(
        "mma.sync.aligned.m16n8k16.row.col.f32.bf16.bf16.f32 "
        "{%0,%1,%2,%3}, {%4,%5,%6,%7}, {%8,%9}, {%0,%1,%2,%3};"
        : "+f"(c[0]), "+f"(c[1]), "+f"(c[2]), "+f"(c[3])
        : "r"(a[0]), "r"(a[1]), "r"(a[2]), "r"(a[3]), "r"(b[0]), "r"(b[1]));
}

__device__ __forceinline__ unsigned packbf(float a, float b)
{
    bf162 t = __floats2bfloat162_rn(a, b);
    return *reinterpret_cast<unsigned*>(&t);
}

__device__ __forceinline__ float gelu_exact(float x)
{
    return 0.5f * x * (1.0f + erff(x * 0.70710678118654752f));
}

// ---------------------------------------------------------------------------
// LayerNorm + split to bf16 hi/lo. One block per row, 256 threads.
// ---------------------------------------------------------------------------
__global__ __launch_bounds__(256)
void ln_split_kernel(const float* __restrict__ x, const float* __restrict__ w,
                     const float* __restrict__ b, bf16* __restrict__ oh,
                     bf16* __restrict__ ol)
{
    __shared__ float red[8];
    __shared__ float bcast;
    const int row = blockIdx.x;
    const int tid = threadIdx.x;
    const int lane = tid & 31, warp = tid >> 5;

    float4 v = ((const float4*)(x + (size_t)row * DD))[tid];

    float s = v.x + v.y + v.z + v.w;
    #pragma unroll
    for (int o = 16; o > 0; o >>= 1) s += __shfl_xor_sync(0xffffffffu, s, o);
    if (lane == 0) red[warp] = s;
    __syncthreads();
    if (tid < 8) {
        float t = red[tid];
        #pragma unroll
        for (int o = 4; o > 0; o >>= 1) t += __shfl_xor_sync(0xffu, t, o);
        if (tid == 0) bcast = t;
    }
    __syncthreads();
    const float mean = bcast * (1.0f / DD);
    __syncthreads();

    float dx0 = v.x - mean, dx1 = v.y - mean, dx2 = v.z - mean, dx3 = v.w - mean;
    float sq = dx0*dx0 + dx1*dx1 + dx2*dx2 + dx3*dx3;
    #pragma unroll
    for (int o = 16; o > 0; o >>= 1) sq += __shfl_xor_sync(0xffffffffu, sq, o);
    if (lane == 0) red[warp] = sq;
    __syncthreads();
    if (tid < 8) {
        float t = red[tid];
        #pragma unroll
        for (int o = 4; o > 0; o >>= 1) t += __shfl_xor_sync(0xffu, t, o);
        if (tid == 0) bcast = t;
    }
    __syncthreads();
    const float inv = rsqrtf(bcast * (1.0f / DD) + EPSLN);

    float4 wv = ((const float4*)w)[tid];
    float4 bv = ((const float4*)b)[tid];
    float o0 = dx0 * inv * wv.x + bv.x;
    float o1 = dx1 * inv * wv.y + bv.y;
    float o2 = dx2 * inv * wv.z + bv.z;
    float o3 = dx3 * inv * wv.w + bv.w;

    bf16 h0,h1,h2,h3,l0,l1,l2,l3;
    split2(o0,h0,l0); split2(o1,h1,l1); split2(o2,h2,l2); split2(o3,h3,l3);
    bf162* H = (bf162*)(oh + (size_t)row * DD + tid * 4);
    bf162* L = (bf162*)(ol + (size_t)row * DD + tid * 4);
    bf162 t0; t0.x = h0; t0.y = h1; H[0] = t0;
    bf162 t1; t1.x = h2; t1.y = h3; H[1] = t1;
    bf162 t2; t2.x = l0; t2.y = l1; L[0] = t2;
    bf162 t3; t3.x = l2; t3.y = l3; L[1] = t3;
}

// ---------------------------------------------------------------------------
// Concatenate QKV biases into g_bias[3072]
// ---------------------------------------------------------------------------
__global__ void concat_bias(const float* __restrict__ bq,
                            const float* __restrict__ bk,
                            const float* __restrict__ bv,
                            float* __restrict__ out)
{
    int i = blockIdx.x * blockDim.x + threadIdx.x;
    float v;
    if (i < DD) v = bq[i];
    else if (i < 2*DD) v = bk[i - DD];
    else v = bv[i - 2*DD];
    out[i] = v;
}

// ---------------------------------------------------------------------------
// Transpose + split (generic): in fp32 [R][C] at in + z*R*C
// out[(z*C + c)*R + r] = split(in[z][r][c])
// ---------------------------------------------------------------------------
__global__ __launch_bounds__(256)
void tsplit_kernel(const float* __restrict__ in, bf16* __restrict__ oh,
                   bf16* __restrict__ ol, int R, int C)
{
    __shared__ float t[32][33];
    const int tx = threadIdx.x, ty = threadIdx.y;
    const int c0 = blockIdx.x * 32, r0 = blockIdx.y * 32, z = blockIdx.z;
    const float* src = in + (size_t)z * R * C;
    #pragma unroll
    for (int i = 0; i < 4; i++)
        t[ty + 8*i][tx] = src[(size_t)(r0 + ty + 8*i) * C + c0 + tx];
    __syncthreads();
    #pragma unroll
    for (int i = 0; i < 4; i++) {
        int c = c0 + ty + 8*i;
        float v = t[tx][ty + 8*i];
        size_t o = (size_t)(z * C + c) * R + r0 + tx;
        bf16 h, l; split2(v, h, l);
        oh[o] = h; ol[o] = l;
    }
}

// ---------------------------------------------------------------------------
// Transpose + split for QKV weights: z = 0..47 -> (which = z/16, head = z%16)
// Writes B rows n = which*1024 + head*64 + c
// ---------------------------------------------------------------------------
__global__ __launch_bounds__(256)
void tsplit_qkv(const float* __restrict__ wq, const float* __restrict__ wk,
                const float* __restrict__ wv, bf16* __restrict__ oh,
                bf16* __restrict__ ol)
{
    __shared__ float t[32][33];
    const int tx = threadIdx.x, ty = threadIdx.y;
    const int c0 = blockIdx.x * 32, r0 = blockIdx.y * 32;
    const int z = blockIdx.z;
    const int which = z >> 4, h = z & 15;
    const float* src = (which == 0 ? wq : (which == 1 ? wk : wv))
                       + (size_t)h * DD * DHH;
    #pragma unroll
    for (int i = 0; i < 4; i++)
        t[ty + 8*i][tx] = src[(size_t)(r0 + ty + 8*i) * DHH + c0 + tx];
    __syncthreads();
    #pragma unroll
    for (int i = 0; i < 4; i++) {
        int c = c0 + ty + 8*i;
        float v = t[tx][ty + 8*i];
        size_t n = (size_t)which * DD + h * DHH + c;
        size_t off = n * DD + r0 + tx;
        bf16 hh, ll; split2(v, hh, ll);
        oh[off] = hh; ol[off] = ll;
    }
}

// ---------------------------------------------------------------------------
// Split-bf16 tensor-core GEMM: C[M,N] = A[M,K] @ B[K,N]
// A hi/lo bf16 row-major [M][K]; B hi/lo bf16 [N][K].
// C = Ah*Bh + Al*Bh + Ah*Bl. BM=BN=128, BK=32, 256 thr, 2-stage cp.async.
// EPI: 1=bias+gelu->split  2=bias+res->fp32  3=QKV: bias+scale->split
// ---------------------------------------------------------------------------
#define EPI_BIAS_GELU  1
#define EPI_BIAS_RES   2
#define EPI_QKV        3

#define ASTR 40
#define TSZ  (128*ASTR)
#define STG  (4*TSZ)

template <int EPI>
__global__ __launch_bounds__(256, 2)
void gemm_bf16(const bf16* __restrict__ Ah, const bf16* __restrict__ Al,
               const bf16* __restrict__ Bh, const bf16* __restrict__ Bl,
               const float* __restrict__ bias, const float* __restrict__ Rm,
               float* __restrict__ Cf, bf16* __restrict__ Oh,
               bf16* __restrict__ Ol, int M, int N, int K)
{
    extern __shared__ bf16 sm[];
    const int tid = threadIdx.x;
    const int bx = blockIdx.x, by = blockIdx.y;
    const int warp = tid >> 5, lane = tid & 31;
    const int wm = warp >> 1, wn = warp & 1;

    const int lrow = tid >> 1;
    const int lcol = (tid & 1) * 16;
    const bf16* gAh = Ah + (size_t)(by * 128 + lrow) * K + lcol;
    const bf16* gAl = Al + (size_t)(by * 128 + lrow) * K + lcol;
    const bf16* gBh = Bh + (size_t)(bx * 128 + lrow) * K + lcol;
    const bf16* gBl = Bl + (size_t)(bx * 128 + lrow) * K + lcol;
    const uint32_t sbase = cvta_s(sm);
    const uint32_t soff = (lrow * ASTR + lcol) * 2;

    float acc[2][8][4];
    #pragma unroll
    for (int i = 0; i < 2; i++)
        #pragma unroll
        for (int j = 0; j < 8; j++)
            #pragma unroll
            for (int q = 0; q < 4; q++) acc[i][j][q] = 0.0f;

    const int a_r = (lane & 7) + ((lane >> 3) & 1) * 8;
    const int a_c = (lane >> 4) * 8;
    const int b_r = (lane & 7) + (lane >> 4) * 8;
    const int b_c = ((lane >> 3) & 1) * 8;

    const int T = K / 32;

    auto issue = [&](int s, int kk) {
        uint32_t st = sbase + (uint32_t)s * STG * 2;
        cp16(st + soff,              gAh + kk);
        cp16(st + soff + 16,         gAh + kk + 8);
        cp16(st + TSZ*2 + soff,      gAl + kk);
        cp16(st + TSZ*2 + soff + 16, gAl + kk + 8);
        cp16(st + TSZ*4 + soff,      gBh + kk);
        cp16(st + TSZ*4 + soff + 16, gBh + kk + 8);
        cp16(st + TSZ*6 + soff,      gBl + kk);
        cp16(st + TSZ*6 + soff + 16, gBl + kk + 8);
        asm volatile("cp.async.commit_group;");
    };

    issue(0, 0);

    for (int t = 0; t < T; t++) {
        if (t + 1 < T) {
            issue((t + 1) & 1, (t + 1) * 32);
            asm volatile("cp.async.wait_group 1;");
        } else {
            asm volatile("cp.async.wait_group 0;");
        }
        __syncthreads();

        const uint32_t st = sbase + (uint32_t)(t & 1) * STG * 2;
        const uint32_t sAh = st;
        const uint32_t sAl = st + TSZ * 2;
        const uint32_t sBh = st + TSZ * 4;
        const uint32_t sBl = st + TSZ * 6;

        #pragma unroll
        for (int kc = 0; kc < 2; kc++) {
            unsigned ah[2][4], al[2][4];
            #pragma unroll
            for (int mf = 0; mf < 2; mf++) {
                uint32_t ao = ((wm*32 + mf*16 + a_r) * ASTR + kc*16 + a_c) * 2;
                ldsm4(ah[mf], sAh + ao);
                ldsm4(al[mf], sAl + ao);
            }
            #pragma unroll
            for (int p = 0; p < 4; p++) {
                unsigned bh4[4], bl4[4];
                uint32_t bo = ((wn*64 + p*16 + b_r) * ASTR + kc*16 + b_c) * 2;
                ldsm4(bh4, sBh + bo);
                ldsm4(bl4, sBl + bo);
                #pragma unroll
                for (int mf = 0; mf < 2; mf++) {
                    mma16816(acc[mf][2*p],     ah[mf], bh4);
                    mma16816(acc[mf][2*p + 1], ah[mf], bh4 + 2);
                    mma16816(acc[mf][2*p],     al[mf], bh4);
                    mma16816(acc[mf][2*p + 1], al[mf], bh4 + 2);
                    mma16816(acc[mf][2*p],     ah[mf], bl4);
                    mma16816(acc[mf][2*p + 1], ah[mf], bl4 + 2);
                }
            }
        }
        __syncthreads();
    }

    const int er = by * 128 + wm * 32 + (lane >> 2);
    const int ec = bx * 128 + wn * 64 + (lane & 3) * 2;
    #pragma unroll
    for (int mf = 0; mf < 2; mf++) {
        #pragma unroll
        for (int nf = 0; nf < 8; nf++) {
            int c = ec + nf * 8;
            float b0 = bias[c], b1 = bias[c + 1];
            #pragma unroll
            for (int half = 0; half < 2; half++) {
                int r = er + mf * 16 + half * 8;
                float v0 = acc[mf][nf][half * 2 + 0] + b0;
                float v1 = acc[mf][nf][half * 2 + 1] + b1;
                if (EPI == EPI_BIAS_GELU || EPI == EPI_QKV) {
                    if (EPI == EPI_BIAS_GELU) {
                        v0 = gelu_exact(v0); v1 = gelu_exact(v1);
                    } else {
                        float sc = (c < DD) ? 0.125f : 1.0f;
                        v0 *= sc; v1 *= sc;
                    }
                    bf16 h0,h1,l0,l1;
                    split2(v0,h0,l0); split2(v1,h1,l1);
                    bf162 th; th.x = h0; th.y = h1;
                    bf162 tl; tl.x = l0; tl.y = l1;
                    *(bf162*)(Oh + (size_t)r * N + c) = th;
                    *(bf162*)(Ol + (size_t)r * N + c) = tl;
                } else {
                    float2 rr = *(const float2*)(Rm + (size_t)r * N + c);
                    v0 += rr.x; v1 += rr.y;
                    float2 o; o.x = v0; o.y = v1;
                    *(float2*)(Cf + (size_t)r * N + c) = o;
                }
            }
        }
    }
}

// ---------------------------------------------------------------------------
// Tensor-core flash attention with split-bf16 precision.
// Grid (32 q-tiles, 32 b*h), 128 threads (4 warps); warp w owns q rows
// [w*16, w*16+16). K/V tiles of 64 tokens, double-buffered cp.async.
// ---------------------------------------------------------------------------
#define AQS   72                     // smem row stride (bf16 elems), 144B
#define ATILE (64*AQS)               // elems per 64x64 tile
#define ATTN_SMEM ((2*ATILE + 8*ATILE) * 2)   // Qh,Ql + 2 stages * 4 tensors

__global__ __launch_bounds__(128, 2)
void attn_mma(const bf16* __restrict__ qkvh, const bf16* __restrict__ qkvl,
              bf16* __restrict__ zh, bf16* __restrict__ zl)
{
    extern __shared__ bf16 smb[];
    const uint32_t sbase = cvta_s(smb);
    const int tid  = threadIdx.x;
    const int warp = tid >> 5, lane = tid & 31;
    const int qt = blockIdx.x;
    const int bh = blockIdx.y;
    const int h  = bh & 15;
    const int hcol = h * DHH;
    const int tokbase = (bh >> 4) * SS;     // batch offset (THE round-4 fix)

    // smem element offsets
    const uint32_t oQh = 0, oQl = ATILE;
    auto stageoff = [](int s) { return (uint32_t)(2*ATILE + s*4*ATILE); };

    // ---- async tile loader: 64 rows x 64 bf16, 4x cp16 per thread ----
    const int ldrow = tid >> 1;
    const int ldc0  = (tid & 1) * 32;
    auto ld_tensor = [&](uint32_t selems, const bf16* g, int tok0, int coff) {
        const bf16* gp = g + (size_t)(tok0 + ldrow) * (3*DD) + coff + ldc0;
        uint32_t sp = sbase + (selems + ldrow * AQS + ldc0) * 2;
        cp16(sp,      gp);
        cp16(sp + 16, gp + 8);
        cp16(sp + 32, gp + 16);
        cp16(sp + 48, gp + 24);
    };
    auto issue_kv = [&](int s, int kt) {
        int tok0 = tokbase + kt * 64;
        uint32_t so = stageoff(s);
        ld_tensor(so,           qkvh, tok0, DD   + hcol);   // Kh
        ld_tensor(so + ATILE,   qkvl, tok0, DD   + hcol);   // Kl
        ld_tensor(so + 2*ATILE, qkvh, tok0, 2*DD + hcol);   // Vh
        ld_tensor(so + 3*ATILE, qkvl, tok0, 2*DD + hcol);   // Vl
        asm volatile("cp.async.commit_group;");
    };

    // ---- issue Q + first KV stage ----
    {
        int tok0 = tokbase + qt * 64;
        ld_tensor(oQh, qkvh, tok0, hcol);
        ld_tensor(oQl, qkvl, tok0, hcol);
        issue_kv(0, 0);   // commit covers Q + stage 0
    }

    // fragment lane decodes
    const int a_r  = (lane & 7) + ((lane >> 3) & 1) * 8;   // A (row-major)
    const int a_c  = (lane >> 4) * 8;
    const int kb_r = (lane & 7) + (lane >> 4) * 8;         // B no-trans
    const int kb_c = ((lane >> 3) & 1) * 8;
    const int vb_r = (lane & 7) + ((lane >> 3) & 1) * 8;   // B trans
    const int vb_c = (lane >> 4) * 8;

    unsigned qh[4][4], ql[4][4];
    float o[8][4];
    #pragma unroll
    for (int j = 0; j < 8; j++)
        #pragma unroll
        for (int q = 0; q < 4; q++) o[j][q] = 0.0f;
    float m0 = -INFINITY, m1 = -INFINITY, l0 = 0.0f, l1 = 0.0f;

    const int r0 = lane >> 2;                 // row within warp block (0..7)
    const int colq = 2 * (lane & 3);          // col pair base within n-block

    for (int kt = 0; kt <= qt; kt++) {
        if (kt + 1 <= qt) {
            issue_kv((kt + 1) & 1, kt + 1);
            asm volatile("cp.async.wait_group 1;");
        } else {
            asm volatile("cp.async.wait_group 0;");
        }
        __syncthreads();

        if (kt == 0) {
            // preload Q fragments (once)
            #pragma unroll
            for (int kc = 0; kc < 4; kc++) {
                uint32_t ao = ((warp*16 + a_r) * AQS + kc*16 + a_c) * 2;
                ldsm4(qh[kc], sbase + (oQh)*2 + ao);
                ldsm4(ql[kc], sbase + (oQl)*2 + ao);
            }
        }

        const uint32_t so = stageoff(kt & 1);
        const uint32_t sKh = sbase + so * 2;
        const uint32_t sKl = sbase + (so + ATILE) * 2;
        const uint32_t sVh = sbase + (so + 2*ATILE) * 2;
        const uint32_t sVl = sbase + (so + 3*ATILE) * 2;

        // ---- S = Q @ K^T (3-term split) ----
        float s[8][4];
        #pragma unroll
        for (int j = 0; j < 8; j++)
            #pragma unroll
            for (int q = 0; q < 4; q++) s[j][q] = 0.0f;

        #pragma unroll
        for (int jp = 0; jp < 4; jp++) {
            #pragma unroll
            for (int kc = 0; kc < 4; kc++) {
                unsigned kh4[4], kl4[4];
                uint32_t ko = ((jp*16 + kb_r) * AQS + kc*16 + kb_c) * 2;
                ldsm4(kh4, sKh + ko);
                ldsm4(kl4, sKl + ko);
                mma16816(s[2*jp],   qh[kc], kh4);
                mma16816(s[2*jp+1], qh[kc], kh4 + 2);
                mma16816(s[2*jp],   ql[kc], kh4);
                mma16816(s[2*jp+1], ql[kc], kh4 + 2);
                mma16816(s[2*jp],   qh[kc], kl4);
                mma16816(s[2*jp+1], qh[kc], kl4 + 2);
            }
        }

        // ---- causal mask on diagonal tile ----
        if (kt == qt) {
            const int rg0 = warp*16 + r0;     // row within 64-tile
            #pragma unroll
            for (int j = 0; j < 8; j++) {
                int cg = j*8 + colq;
                if (cg     > rg0) s[j][0] = -1e30f;
                if (cg + 1 > rg0) s[j][1] = -1e30f;
                if (cg     > rg0 + 8) s[j][2] = -1e30f;
                if (cg + 1 > rg0 + 8) s[j][3] = -1e30f;
            }
        }

        // ---- online softmax ----
        float vmax0 = -INFINITY, vmax1 = -INFINITY;
        #pragma unroll
        for (int j = 0; j < 8; j++) {
            vmax0 = fmaxf(vmax0, fmaxf(s[j][0], s[j][1]));
            vmax1 = fmaxf(vmax1, fmaxf(s[j][2], s[j][3]));
        }
        vmax0 = fmaxf(vmax0, __shfl_xor_sync(0xffffffffu, vmax0, 1));
        vmax0 = fmaxf(vmax0, __shfl_xor_sync(0xffffffffu, vmax0, 2));
        vmax1 = fmaxf(vmax1, __shfl_xor_sync(0xffffffffu, vmax1, 1));
        vmax1 = fmaxf(vmax1, __shfl_xor_sync(0xffffffffu, vmax1, 2));

        float mn0 = fmaxf(m0, vmax0), mn1 = fmaxf(m1, vmax1);
        float f0 = __expf(m0 - mn0), f1 = __expf(m1 - mn1);
        m0 = mn0; m1 = mn1;

        float rs0 = 0.0f, rs1 = 0.0f;
        #pragma unroll
        for (int j = 0; j < 8; j++) {
            s[j][0] = __expf(s[j][0] - mn0);
            s[j][1] = __expf(s[j][1] - mn0);
            s[j][2] = __expf(s[j][2] - mn1);
            s[j][3] = __expf(s[j][3] - mn1);
            rs0 += s[j][0] + s[j][1];
            rs1 += s[j][2] + s[j][3];
        }
        rs0 += __shfl_xor_sync(0xffffffffu, rs0, 1);
        rs0 += __shfl_xor_sync(0xffffffffu, rs0, 2);
        rs1 += __shfl_xor_sync(0xffffffffu, rs1, 1);
        rs1 += __shfl_xor_sync(0xffffffffu, rs1, 2);
        l0 = l0 * f0 + rs0;
        l1 = l1 * f1 + rs1;

        #pragma unroll
        for (int j = 0; j < 8; j++) {
            o[j][0] *= f0; o[j][1] *= f0;
            o[j][2] *= f1; o[j][3] *= f1;
        }

        // ---- repack P (accum layout) into A fragments, hi/lo split ----
        unsigned ph[4][4], pl[4][4];
        #pragma unroll
        for (int jc = 0; jc < 4; jc++) {
            const int j0 = 2*jc, j1 = 2*jc + 1;
            #define SPLITPAIR(a, b, HI, LOI)                       \
                {  bf16 _h0,_l0,_h1,_l1;                           \
                   split2(a,_h0,_l0); split2(b,_h1,_l1);           \
                   HI  = packbf(__bfloat162float(_h0), __bfloat162float(_h1)); \
                   LOI = packbf(__bfloat162float(_l0), __bfloat162float(_l1)); }
            SPLITPAIR(s[j0][0], s[j0][1], ph[jc][0], pl[jc][0]);
            SPLITPAIR(s[j0][2], s[j0][3], ph[jc][1], pl[jc][1]);
            SPLITPAIR(s[j1][0], s[j1][1], ph[jc][2], pl[jc][2]);
            SPLITPAIR(s[j1][2], s[j1][3], ph[jc][3], pl[jc][3]);
            #undef SPLITPAIR
        }

        // ---- O += P @ V (3-term split) ----
        #pragma unroll
        for (int jc = 0; jc < 4; jc++) {
            #pragma unroll
            for (int np = 0; np < 4; np++) {
                unsigned vh4[4], vl4[4];
                uint32_t vo = ((jc*16 + vb_r) * AQS + np*16 + vb_c) * 2;
                ldsm4t(vh4, sVh + vo);
                ldsm4t(vl4, sVl + vo);
                mma16816(o[2*np],   ph[jc], vh4);
                mma16816(o[2*np+1], ph[jc], vh4 + 2);
                mma16816(o[2*np],   pl[jc], vh4);
                mma16816(o[2*np+1], pl[jc], vh4 + 2);
                mma16816(o[2*np],   ph[jc], vl4);
                mma16816(o[2*np+1], ph[jc], vl4 + 2);
            }
        }
        __syncthreads();
    }

    // ---- finalize: z = O / l, split to bf16 hi/lo ----
    const float il0 = 1.0f / l0, il1 = 1.0f / l1;
    const int row0 = tokbase + qt*64 + warp*16 + r0;
    #pragma unroll
    for (int j = 0; j < 8; j++) {
        int c = hcol + j*8 + colq;
        float a0 = o[j][0] * il0, a1 = o[j][1] * il0;
        float b0 = o[j][2] * il1, b1 = o[j][3] * il1;
        bf16 h0,lo0,h1,lo1;
        split2(a0,h0,lo0); split2(a1,h1,lo1);
        bf162 th; th.x = h0; th.y = h1;
        bf162 tl; tl.x = lo0; tl.y = lo1;
        *(bf162*)(zh + (size_t)row0 * DD + c) = th;
        *(bf162*)(zl + (size_t)row0 * DD + c) = tl;
        split2(b0,h0,lo0); split2(b1,h1,lo1);
        th.x = h0; th.y = h1;
        tl.x = lo0; tl.y = lo1;
        *(bf162*)(zh + (size_t)(row0 + 8) * DD + c) = th;
        *(bf162*)(zl + (size_t)(row0 + 8) * DD + c) = tl;
    }
}

// ---------------------------------------------------------------------------
// Host launcher
// ---------------------------------------------------------------------------
#define GEMM_SMEM (2 * STG * 2)

extern "C" void kernel_launch(void* const* d_in, const int* in_sizes, int n_in,
                              void* d_out, int out_size)
{
    (void)in_sizes; (void)n_in; (void)out_size;
    const float* resid = (const float*)d_in[0];
    const float* ln1w  = (const float*)d_in[1];
    const float* ln1b  = (const float*)d_in[2];
    const float* WQ    = (const float*)d_in[3];
    const float* bQ    = (const float*)d_in[4];
    const float* WK    = (const float*)d_in[5];
    const float* bK    = (const float*)d_in[6];
    const float* WV    = (const float*)d_in[7];
    const float* bV    = (const float*)d_in[8];
    const float* WO    = (const float*)d_in[9];
    const float* bO    = (const float*)d_in[10];
    const float* ln2w  = (const float*)d_in[11];
    const float* ln2b  = (const float*)d_in[12];
    const float* Win   = (const float*)d_in[13];
    const float* bin   = (const float*)d_in[14];
    const float* Wout  = (const float*)d_in[15];
    const float* bout  = (const float*)d_in[16];

    float *mid, *biasqkv;
    bf16 *xh, *xl, *qkvh, *qkvl, *acth, *actl, *wh, *wl;
    cudaGetSymbolAddress((void**)&mid,   g_mid);
    cudaGetSymbolAddress((void**)&biasqkv, g_bias);
    cudaGetSymbolAddress((void**)&xh,    g_xh);
    cudaGetSymbolAddress((void**)&xl,    g_xl);
    cudaGetSymbolAddress((void**)&qkvh,  g_qkvh);
    cudaGetSymbolAddress((void**)&qkvl,  g_qkvl);
    cudaGetSymbolAddress((void**)&acth,  g_acth);
    cudaGetSymbolAddress((void**)&actl,  g_actl);
    cudaGetSymbolAddress((void**)&wh,    g_wh);
    cudaGetSymbolAddress((void**)&wl,    g_wl);

    cudaFuncSetAttribute(attn_mma, cudaFuncAttributeMaxDynamicSharedMemorySize,
                         ATTN_SMEM);
    cudaFuncSetAttribute(gemm_bf16<EPI_QKV>,
                         cudaFuncAttributeMaxDynamicSharedMemorySize, GEMM_SMEM);
    cudaFuncSetAttribute(gemm_bf16<EPI_BIAS_GELU>,
                         cudaFuncAttributeMaxDynamicSharedMemorySize, GEMM_SMEM);
    cudaFuncSetAttribute(gemm_bf16<EPI_BIAS_RES>,
                         cudaFuncAttributeMaxDynamicSharedMemorySize, GEMM_SMEM);

    dim3 tb(32, 8);

    // 1) LN1 -> split
    ln_split_kernel<<<NTOK, 256>>>(resid, ln1w, ln1b, xh, xl);

    // 2) fused QKV: weights + bias prep, one big GEMM (Q prescaled by 1/8)
    concat_bias<<<12, 256>>>(bQ, bK, bV, biasqkv);
    tsplit_qkv<<<dim3(DHH/32, DD/32, 48), tb>>>(WQ, WK, WV, wh, wl);
    dim3 g3072(3*DD/128, NTOK/128);
    gemm_bf16<EPI_QKV><<<g3072, 256, GEMM_SMEM>>>(xh, xl, wh, wl, biasqkv,
                                                  nullptr, nullptr, qkvh, qkvl,
                                                  NTOK, 3*DD, DD);

    // 3) tensor-core causal attention -> z split (into xh/xl)
    dim3 ga(SS / 64, BB * HH);
    attn_mma<<<ga, 128, ATTN_SMEM>>>(qkvh, qkvl, xh, xl);

    // 4) O-projection + residual -> mid
    dim3 g1024(DD/128, NTOK/128);
    tsplit_kernel<<<dim3(DD/32, DD/32, 1), tb>>>(WO, wh, wl, DD, DD);
    gemm_bf16<EPI_BIAS_RES><<<g1024, 256, GEMM_SMEM>>>(xh, xl, wh, wl, bO, resid,
                                                       mid, nullptr, nullptr,
                                                       NTOK, DD, DD);

    // 5) LN2 -> split
    ln_split_kernel<<<NTOK, 256>>>(mid, ln2w, ln2b, xh, xl);

    // 6) MLP in + exact GELU -> split act
    dim3 g4096(DMM/128, NTOK/128);
    tsplit_kernel<<<dim3(DMM/32, DD/32, 1), tb>>>(Win, wh, wl, DD, DMM);
    gemm_bf16<EPI_BIAS_GELU><<<g4096, 256, GEMM_SMEM>>>(xh, xl, wh, wl, bin,
                                                        nullptr, nullptr,
                                                        acth, actl,
                                                        NTOK, DMM, DD);

    // 7) MLP out + bias + residual -> d_out
    tsplit_kernel<<<dim3(DD/32, DMM/32, 1), tb>>>(Wout, wh, wl, DMM, DD);
    gemm_bf16<EPI_BIAS_RES><<<g1024, 256, GEMM_SMEM>>>(acth, actl, wh, wl, bout,
                                                       mid, (float*)d_out,
                                                       nullptr, nullptr,
                                                       NTOK, DD, DMM);
}

// round 8
// speedup vs baseline: 2.6621x; 1.0711x over previous
#include <cuda_runtime.h>
#include <cuda_bf16.h>
#include <math.h>
#include <stdint.h>

// Problem constants
#define BB   2
#define SS   2048
#define DD   1024
#define HH   16
#define DHH  64
#define DMM  4096
#define NTOK (BB*SS)          // 4096
#define EPSLN 1e-5f

typedef __nv_bfloat16  bf16;
typedef __nv_bfloat162 bf162;

// ---------------------------------------------------------------------------
// Device scratch
// ---------------------------------------------------------------------------
__device__ float g_mid[NTOK*DD];
__device__ float g_bias[3*DD];        // concatenated QKV bias
__device__ bf16  g_xh [NTOK*DD];      // split activations (hi)
__device__ bf16  g_xl [NTOK*DD];      // split activations (lo)
__device__ bf16  g_qkvh[NTOK*3*DD];   // fused QKV output (hi)
__device__ bf16  g_qkvl[NTOK*3*DD];   // fused QKV output (lo)
__device__ bf16  g_acth[NTOK*DMM];    // gelu output split (hi)
__device__ bf16  g_actl[NTOK*DMM];    // gelu output split (lo)
__device__ bf16  g_wh [DD*DMM];       // split transposed weight (hi) - reused
__device__ bf16  g_wl [DD*DMM];       // split transposed weight (lo) - reused

// ---------------------------------------------------------------------------
// Helpers
// ---------------------------------------------------------------------------
__device__ __forceinline__ void split2(float x, bf16& h, bf16& l)
{
    h = __float2bfloat16_rn(x);
    l = __float2bfloat16_rn(x - __bfloat162float(h));
}

__device__ __forceinline__ uint32_t cvta_s(const void* p)
{
    return (uint32_t)__cvta_generic_to_shared(p);
}

__device__ __forceinline__ void cp16(uint32_t s, const void* g)
{
    asm volatile("cp.async.cg.shared.global [%0], [%1], 16;" :: "r"(s), "l"(g));
}

__device__ __forceinline__ void ldsm4(unsigned r[4], uint32_t a)
{
    asm volatile("ldmatrix.sync.aligned.m8n8.x4.shared.b16 {%0,%1,%2,%3}, [%4];"
                 : "=r"(r[0]), "=r"(r[1]), "=r"(r[2]), "=r"(r[3]) : "r"(a));
}

__device__ __forceinline__ void ldsm4t(unsigned r[4], uint32_t a)
{
    asm volatile("ldmatrix.sync.aligned.m8n8.x4.trans.shared.b16 {%0,%1,%2,%3}, [%4];"
                 : "=r"(r[0]), "=r"(r[1]), "=r"(r[2]), "=r"(r[3]) : "r"(a));
}

__device__ __forceinline__ void mma16816(float c[4], const unsigned a[4],
                                         const unsigned b[2])
{
    asm volatile(
        "mma.sync.aligned.m16n8k16.row.col.f32.bf16.bf16.f32 "
        "{%0,%1,%2,%3}, {%4,%5,%6,%7}, {%8,%9}, {%0,%1,%2,%3};"
        : "+f"(c[0]), "+f"(c[1]), "+f"(c[2]), "+f"(c[3])
        : "r"(a[0]), "r"(a[1]), "r"(a[2]), "r"(a[3]), "r"(b[0]), "r"(b[1]));
}

__device__ __forceinline__ unsigned packbf(float a, float b)
{
    bf162 t = __floats2bfloat162_rn(a, b);
    return *reinterpret_cast<unsigned*>(&t);
}

__device__ __forceinline__ float gelu_exact(float x)
{
    return 0.5f * x * (1.0f + erff(x * 0.70710678118654752f));
}

// ---------------------------------------------------------------------------
// LayerNorm + split to bf16 hi/lo. One block per row, 256 threads.
// ---------------------------------------------------------------------------
__global__ __launch_bounds__(256)
void ln_split_kernel(const float* __restrict__ x, const float* __restrict__ w,
                     const float* __restrict__ b, bf16* __restrict__ oh,
                     bf16* __restrict__ ol)
{
    __shared__ float red[8];
    __shared__ float bcast;
    const int row = blockIdx.x;
    const int tid = threadIdx.x;
    const int lane = tid & 31, warp = tid >> 5;

    float4 v = ((const float4*)(x + (size_t)row * DD))[tid];

    float s = v.x + v.y + v.z + v.w;
    #pragma unroll
    for (int o = 16; o > 0; o >>= 1) s += __shfl_xor_sync(0xffffffffu, s, o);
    if (lane == 0) red[warp] = s;
    __syncthreads();
    if (tid < 8) {
        float t = red[tid];
        #pragma unroll
        for (int o = 4; o > 0; o >>= 1) t += __shfl_xor_sync(0xffu, t, o);
        if (tid == 0) bcast = t;
    }
    __syncthreads();
    const float mean = bcast * (1.0f / DD);
    __syncthreads();

    float dx0 = v.x - mean, dx1 = v.y - mean, dx2 = v.z - mean, dx3 = v.w - mean;
    float sq = dx0*dx0 + dx1*dx1 + dx2*dx2 + dx3*dx3;
    #pragma unroll
    for (int o = 16; o > 0; o >>= 1) sq += __shfl_xor_sync(0xffffffffu, sq, o);
    if (lane == 0) red[warp] = sq;
    __syncthreads();
    if (tid < 8) {
        float t = red[tid];
        #pragma unroll
        for (int o = 4; o > 0; o >>= 1) t += __shfl_xor_sync(0xffu, t, o);
        if (tid == 0) bcast = t;
    }
    __syncthreads();
    const float inv = rsqrtf(bcast * (1.0f / DD) + EPSLN);

    float4 wv = ((const float4*)w)[tid];
    float4 bv = ((const float4*)b)[tid];
    float o0 = dx0 * inv * wv.x + bv.x;
    float o1 = dx1 * inv * wv.y + bv.y;
    float o2 = dx2 * inv * wv.z + bv.z;
    float o3 = dx3 * inv * wv.w + bv.w;

    bf16 h0,h1,h2,h3,l0,l1,l2,l3;
    split2(o0,h0,l0); split2(o1,h1,l1); split2(o2,h2,l2); split2(o3,h3,l3);
    bf162* H = (bf162*)(oh + (size_t)row * DD + tid * 4);
    bf162* L = (bf162*)(ol + (size_t)row * DD + tid * 4);
    bf162 t0; t0.x = h0; t0.y = h1; H[0] = t0;
    bf162 t1; t1.x = h2; t1.y = h3; H[1] = t1;
    bf162 t2; t2.x = l0; t2.y = l1; L[0] = t2;
    bf162 t3; t3.x = l2; t3.y = l3; L[1] = t3;
}

// ---------------------------------------------------------------------------
// Concatenate QKV biases into g_bias[3072]
// ---------------------------------------------------------------------------
__global__ void concat_bias(const float* __restrict__ bq,
                            const float* __restrict__ bk,
                            const float* __restrict__ bv,
                            float* __restrict__ out)
{
    int i = blockIdx.x * blockDim.x + threadIdx.x;
    float v;
    if (i < DD) v = bq[i];
    else if (i < 2*DD) v = bk[i - DD];
    else v = bv[i - 2*DD];
    out[i] = v;
}

// ---------------------------------------------------------------------------
// Transpose + split (generic): in fp32 [R][C] at in + z*R*C
// out[(z*C + c)*R + r] = split(in[z][r][c])
// ---------------------------------------------------------------------------
__global__ __launch_bounds__(256)
void tsplit_kernel(const float* __restrict__ in, bf16* __restrict__ oh,
                   bf16* __restrict__ ol, int R, int C)
{
    __shared__ float t[32][33];
    const int tx = threadIdx.x, ty = threadIdx.y;
    const int c0 = blockIdx.x * 32, r0 = blockIdx.y * 32, z = blockIdx.z;
    const float* src = in + (size_t)z * R * C;
    #pragma unroll
    for (int i = 0; i < 4; i++)
        t[ty + 8*i][tx] = src[(size_t)(r0 + ty + 8*i) * C + c0 + tx];
    __syncthreads();
    #pragma unroll
    for (int i = 0; i < 4; i++) {
        int c = c0 + ty + 8*i;
        float v = t[tx][ty + 8*i];
        size_t o = (size_t)(z * C + c) * R + r0 + tx;
        bf16 h, l; split2(v, h, l);
        oh[o] = h; ol[o] = l;
    }
}

// ---------------------------------------------------------------------------
// Transpose + split for QKV weights: z = 0..47 -> (which = z/16, head = z%16)
// ---------------------------------------------------------------------------
__global__ __launch_bounds__(256)
void tsplit_qkv(const float* __restrict__ wq, const float* __restrict__ wk,
                const float* __restrict__ wv, bf16* __restrict__ oh,
                bf16* __restrict__ ol)
{
    __shared__ float t[32][33];
    const int tx = threadIdx.x, ty = threadIdx.y;
    const int c0 = blockIdx.x * 32, r0 = blockIdx.y * 32;
    const int z = blockIdx.z;
    const int which = z >> 4, h = z & 15;
    const float* src = (which == 0 ? wq : (which == 1 ? wk : wv))
                       + (size_t)h * DD * DHH;
    #pragma unroll
    for (int i = 0; i < 4; i++)
        t[ty + 8*i][tx] = src[(size_t)(r0 + ty + 8*i) * DHH + c0 + tx];
    __syncthreads();
    #pragma unroll
    for (int i = 0; i < 4; i++) {
        int c = c0 + ty + 8*i;
        float v = t[tx][ty + 8*i];
        size_t n = (size_t)which * DD + h * DHH + c;
        size_t off = n * DD + r0 + tx;
        bf16 hh, ll; split2(v, hh, ll);
        oh[off] = hh; ol[off] = ll;
    }
}

// ---------------------------------------------------------------------------
// Split-bf16 tensor-core GEMM: C[M,N] = A[M,K] @ B[K,N]
// A hi/lo bf16 row-major [M][K]; B hi/lo bf16 [N][K].
// C = Ah*Bh + Al*Bh + Ah*Bl. BM=BN=128, BK=32, 256 thr.
// 3-stage cp.async pipeline; packed 64B rows with SW64 XOR swizzle
// (conflict-free ldmatrix, 32KB/stage -> 3 stages x 2 CTAs fit in smem).
// EPI: 1=bias+gelu->split  2=bias+res->fp32  3=QKV: bias+scale->split
// ---------------------------------------------------------------------------
#define EPI_BIAS_GELU  1
#define EPI_BIAS_RES   2
#define EPI_QKV        3

#define TILE_BYTES 8192            // 128 rows * 64B
#define STG_BYTES  (4*TILE_BYTES)  // Ah,Al,Bh,Bl
#define GEMM_SMEM  (3*STG_BYTES)   // 98304 B

template <int EPI>
__global__ __launch_bounds__(256, 2)
void gemm_bf16(const bf16* __restrict__ Ah, const bf16* __restrict__ Al,
               const bf16* __restrict__ Bh, const bf16* __restrict__ Bl,
               const float* __restrict__ bias, const float* __restrict__ Rm,
               float* __restrict__ Cf, bf16* __restrict__ Oh,
               bf16* __restrict__ Ol, int M, int N, int K)
{
    extern __shared__ bf16 sm[];
    const int tid = threadIdx.x;
    const int bx = blockIdx.x, by = blockIdx.y;
    const int warp = tid >> 5, lane = tid & 31;
    const int wm = warp >> 1, wn = warp & 1;

    // ---- loader mapping: row = tid/2, 32B half-row per thread ----
    const int lrow = tid >> 1;
    const int lhalf = (tid & 1);                 // 0 or 1 -> byte 0/32
    const bf16* gAh = Ah + (size_t)(by * 128 + lrow) * K + lhalf * 16;
    const bf16* gAl = Al + (size_t)(by * 128 + lrow) * K + lhalf * 16;
    const bf16* gBh = Bh + (size_t)(bx * 128 + lrow) * K + lhalf * 16;
    const bf16* gBl = Bl + (size_t)(bx * 128 + lrow) * K + lhalf * 16;
    const uint32_t sbase = cvta_s(sm);
    const uint32_t lxm = (uint32_t)((lrow & 6) << 3);    // swizzle mask
    const uint32_t lso0 = lrow * 64 + ((lhalf * 32)      ^ lxm);
    const uint32_t lso1 = lrow * 64 + ((lhalf * 32 + 16) ^ lxm);

    float acc[2][8][4];
    #pragma unroll
    for (int i = 0; i < 2; i++)
        #pragma unroll
        for (int j = 0; j < 8; j++)
            #pragma unroll
            for (int q = 0; q < 4; q++) acc[i][j][q] = 0.0f;

    // ---- ldmatrix lane decodes (element indices) ----
    const int a_r = (lane & 7) + ((lane >> 3) & 1) * 8;
    const int a_c = (lane >> 4) * 8;
    const int b_r = (lane & 7) + (lane >> 4) * 8;
    const int b_c = ((lane >> 3) & 1) * 8;

    // per-fragment row bases + swizzle masks
    uint32_t arow[2], axm[2];
    #pragma unroll
    for (int mf = 0; mf < 2; mf++) {
        int r = wm*32 + mf*16 + a_r;
        arow[mf] = (uint32_t)r * 64;
        axm[mf]  = (uint32_t)((r & 6) << 3);
    }
    uint32_t brow[4], bxm[4];
    #pragma unroll
    for (int p = 0; p < 4; p++) {
        int r = wn*64 + p*16 + b_r;
        brow[p] = (uint32_t)r * 64;
        bxm[p]  = (uint32_t)((r & 6) << 3);
    }
    const uint32_t acb = (uint32_t)(a_c * 2);
    const uint32_t bcb = (uint32_t)(b_c * 2);

    const int T = K / 32;

    auto issue = [&](int s, int kk) {
        uint32_t st = sbase + (uint32_t)s * STG_BYTES;
        cp16(st + lso0,                gAh + kk);
        cp16(st + lso1,                gAh + kk + 8);
        cp16(st + TILE_BYTES   + lso0, gAl + kk);
        cp16(st + TILE_BYTES   + lso1, gAl + kk + 8);
        cp16(st + TILE_BYTES*2 + lso0, gBh + kk);
        cp16(st + TILE_BYTES*2 + lso1, gBh + kk + 8);
        cp16(st + TILE_BYTES*3 + lso0, gBl + kk);
        cp16(st + TILE_BYTES*3 + lso1, gBl + kk + 8);
        asm volatile("cp.async.commit_group;");
    };

    issue(0, 0);
    if (T > 1) issue(1, 32);

    int stage = 0;
    for (int t = 0; t < T; t++) {
        if (t + 2 < T) {
            issue((stage + 2) % 3, (t + 2) * 32);
            asm volatile("cp.async.wait_group 2;");
        } else if (t + 1 < T) {
            asm volatile("cp.async.wait_group 1;");
        } else {
            asm volatile("cp.async.wait_group 0;");
        }
        __syncthreads();

        const uint32_t st  = sbase + (uint32_t)stage * STG_BYTES;
        const uint32_t sAh = st;
        const uint32_t sAl = st + TILE_BYTES;
        const uint32_t sBh = st + TILE_BYTES*2;
        const uint32_t sBl = st + TILE_BYTES*3;

        #pragma unroll
        for (int kc = 0; kc < 2; kc++) {
            const uint32_t kb = (uint32_t)(kc * 32);
            unsigned ah[2][4], al[2][4];
            #pragma unroll
            for (int mf = 0; mf < 2; mf++) {
                uint32_t ao = arow[mf] + ((kb + acb) ^ axm[mf]);
                ldsm4(ah[mf], sAh + ao);
                ldsm4(al[mf], sAl + ao);
            }
            #pragma unroll
            for (int p = 0; p < 4; p++) {
                unsigned bh4[4], bl4[4];
                uint32_t bo = brow[p] + ((kb + bcb) ^ bxm[p]);
                ldsm4(bh4, sBh + bo);
                ldsm4(bl4, sBl + bo);
                #pragma unroll
                for (int mf = 0; mf < 2; mf++) {
                    mma16816(acc[mf][2*p],     ah[mf], bh4);
                    mma16816(acc[mf][2*p + 1], ah[mf], bh4 + 2);
                    mma16816(acc[mf][2*p],     al[mf], bh4);
                    mma16816(acc[mf][2*p + 1], al[mf], bh4 + 2);
                    mma16816(acc[mf][2*p],     ah[mf], bl4);
                    mma16816(acc[mf][2*p + 1], ah[mf], bl4 + 2);
                }
            }
        }
        __syncthreads();
        stage = (stage + 1) % 3;
    }

    const int er = by * 128 + wm * 32 + (lane >> 2);
    const int ec = bx * 128 + wn * 64 + (lane & 3) * 2;
    #pragma unroll
    for (int mf = 0; mf < 2; mf++) {
        #pragma unroll
        for (int nf = 0; nf < 8; nf++) {
            int c = ec + nf * 8;
            float b0 = bias[c], b1 = bias[c + 1];
            #pragma unroll
            for (int half = 0; half < 2; half++) {
                int r = er + mf * 16 + half * 8;
                float v0 = acc[mf][nf][half * 2 + 0] + b0;
                float v1 = acc[mf][nf][half * 2 + 1] + b1;
                if (EPI == EPI_BIAS_GELU || EPI == EPI_QKV) {
                    if (EPI == EPI_BIAS_GELU) {
                        v0 = gelu_exact(v0); v1 = gelu_exact(v1);
                    } else {
                        float sc = (c < DD) ? 0.125f : 1.0f;
                        v0 *= sc; v1 *= sc;
                    }
                    bf16 h0,h1,l0,l1;
                    split2(v0,h0,l0); split2(v1,h1,l1);
                    bf162 th; th.x = h0; th.y = h1;
                    bf162 tl; tl.x = l0; tl.y = l1;
                    *(bf162*)(Oh + (size_t)r * N + c) = th;
                    *(bf162*)(Ol + (size_t)r * N + c) = tl;
                } else {
                    float2 rr = *(const float2*)(Rm + (size_t)r * N + c);
                    v0 += rr.x; v1 += rr.y;
                    float2 o; o.x = v0; o.y = v1;
                    *(float2*)(Cf + (size_t)r * N + c) = o;
                }
            }
        }
    }
}

// ---------------------------------------------------------------------------
// Tensor-core flash attention with split-bf16 precision. (unchanged)
// ---------------------------------------------------------------------------
#define AQS   72                     // smem row stride (bf16 elems), 144B
#define ATILE (64*AQS)               // elems per 64x64 tile
#define ATTN_SMEM ((2*ATILE + 8*ATILE) * 2)   // Qh,Ql + 2 stages * 4 tensors

__global__ __launch_bounds__(128, 2)
void attn_mma(const bf16* __restrict__ qkvh, const bf16* __restrict__ qkvl,
              bf16* __restrict__ zh, bf16* __restrict__ zl)
{
    extern __shared__ bf16 smb[];
    const uint32_t sbase = cvta_s(smb);
    const int tid  = threadIdx.x;
    const int warp = tid >> 5, lane = tid & 31;
    const int qt = blockIdx.x;
    const int bh = blockIdx.y;
    const int h  = bh & 15;
    const int hcol = h * DHH;
    const int tokbase = (bh >> 4) * SS;     // batch offset

    const uint32_t oQh = 0, oQl = ATILE;
    auto stageoff = [](int s) { return (uint32_t)(2*ATILE + s*4*ATILE); };

    const int ldrow = tid >> 1;
    const int ldc0  = (tid & 1) * 32;
    auto ld_tensor = [&](uint32_t selems, const bf16* g, int tok0, int coff) {
        const bf16* gp = g + (size_t)(tok0 + ldrow) * (3*DD) + coff + ldc0;
        uint32_t sp = sbase + (selems + ldrow * AQS + ldc0) * 2;
        cp16(sp,      gp);
        cp16(sp + 16, gp + 8);
        cp16(sp + 32, gp + 16);
        cp16(sp + 48, gp + 24);
    };
    auto issue_kv = [&](int s, int kt) {
        int tok0 = tokbase + kt * 64;
        uint32_t so = stageoff(s);
        ld_tensor(so,           qkvh, tok0, DD   + hcol);   // Kh
        ld_tensor(so + ATILE,   qkvl, tok0, DD   + hcol);   // Kl
        ld_tensor(so + 2*ATILE, qkvh, tok0, 2*DD + hcol);   // Vh
        ld_tensor(so + 3*ATILE, qkvl, tok0, 2*DD + hcol);   // Vl
        asm volatile("cp.async.commit_group;");
    };

    {
        int tok0 = tokbase + qt * 64;
        ld_tensor(oQh, qkvh, tok0, hcol);
        ld_tensor(oQl, qkvl, tok0, hcol);
        issue_kv(0, 0);
    }

    const int a_r  = (lane & 7) + ((lane >> 3) & 1) * 8;   // A (row-major)
    const int a_c  = (lane >> 4) * 8;
    const int kb_r = (lane & 7) + (lane >> 4) * 8;         // B no-trans
    const int kb_c = ((lane >> 3) & 1) * 8;
    const int vb_r = (lane & 7) + ((lane >> 3) & 1) * 8;   // B trans
    const int vb_c = (lane >> 4) * 8;

    unsigned qh[4][4], ql[4][4];
    float o[8][4];
    #pragma unroll
    for (int j = 0; j < 8; j++)
        #pragma unroll
        for (int q = 0; q < 4; q++) o[j][q] = 0.0f;
    float m0 = -INFINITY, m1 = -INFINITY, l0 = 0.0f, l1 = 0.0f;

    const int r0 = lane >> 2;
    const int colq = 2 * (lane & 3);

    for (int kt = 0; kt <= qt; kt++) {
        if (kt + 1 <= qt) {
            issue_kv((kt + 1) & 1, kt + 1);
            asm volatile("cp.async.wait_group 1;");
        } else {
            asm volatile("cp.async.wait_group 0;");
        }
        __syncthreads();

        if (kt == 0) {
            #pragma unroll
            for (int kc = 0; kc < 4; kc++) {
                uint32_t ao = ((warp*16 + a_r) * AQS + kc*16 + a_c) * 2;
                ldsm4(qh[kc], sbase + (oQh)*2 + ao);
                ldsm4(ql[kc], sbase + (oQl)*2 + ao);
            }
        }

        const uint32_t so = stageoff(kt & 1);
        const uint32_t sKh = sbase + so * 2;
        const uint32_t sKl = sbase + (so + ATILE) * 2;
        const uint32_t sVh = sbase + (so + 2*ATILE) * 2;
        const uint32_t sVl = sbase + (so + 3*ATILE) * 2;

        float s[8][4];
        #pragma unroll
        for (int j = 0; j < 8; j++)
            #pragma unroll
            for (int q = 0; q < 4; q++) s[j][q] = 0.0f;

        #pragma unroll
        for (int jp = 0; jp < 4; jp++) {
            #pragma unroll
            for (int kc = 0; kc < 4; kc++) {
                unsigned kh4[4], kl4[4];
                uint32_t ko = ((jp*16 + kb_r) * AQS + kc*16 + kb_c) * 2;
                ldsm4(kh4, sKh + ko);
                ldsm4(kl4, sKl + ko);
                mma16816(s[2*jp],   qh[kc], kh4);
                mma16816(s[2*jp+1], qh[kc], kh4 + 2);
                mma16816(s[2*jp],   ql[kc], kh4);
                mma16816(s[2*jp+1], ql[kc], kh4 + 2);
                mma16816(s[2*jp],   qh[kc], kl4);
                mma16816(s[2*jp+1], qh[kc], kl4 + 2);
            }
        }

        if (kt == qt) {
            const int rg0 = warp*16 + r0;
            #pragma unroll
            for (int j = 0; j < 8; j++) {
                int cg = j*8 + colq;
                if (cg     > rg0) s[j][0] = -1e30f;
                if (cg + 1 > rg0) s[j][1] = -1e30f;
                if (cg     > rg0 + 8) s[j][2] = -1e30f;
                if (cg + 1 > rg0 + 8) s[j][3] = -1e30f;
            }
        }

        float vmax0 = -INFINITY, vmax1 = -INFINITY;
        #pragma unroll
        for (int j = 0; j < 8; j++) {
            vmax0 = fmaxf(vmax0, fmaxf(s[j][0], s[j][1]));
            vmax1 = fmaxf(vmax1, fmaxf(s[j][2], s[j][3]));
        }
        vmax0 = fmaxf(vmax0, __shfl_xor_sync(0xffffffffu, vmax0, 1));
        vmax0 = fmaxf(vmax0, __shfl_xor_sync(0xffffffffu, vmax0, 2));
        vmax1 = fmaxf(vmax1, __shfl_xor_sync(0xffffffffu, vmax1, 1));
        vmax1 = fmaxf(vmax1, __shfl_xor_sync(0xffffffffu, vmax1, 2));

        float mn0 = fmaxf(m0, vmax0), mn1 = fmaxf(m1, vmax1);
        float f0 = __expf(m0 - mn0), f1 = __expf(m1 - mn1);
        m0 = mn0; m1 = mn1;

        float rs0 = 0.0f, rs1 = 0.0f;
        #pragma unroll
        for (int j = 0; j < 8; j++) {
            s[j][0] = __expf(s[j][0] - mn0);
            s[j][1] = __expf(s[j][1] - mn0);
            s[j][2] = __expf(s[j][2] - mn1);
            s[j][3] = __expf(s[j][3] - mn1);
            rs0 += s[j][0] + s[j][1];
            rs1 += s[j][2] + s[j][3];
        }
        rs0 += __shfl_xor_sync(0xffffffffu, rs0, 1);
        rs0 += __shfl_xor_sync(0xffffffffu, rs0, 2);
        rs1 += __shfl_xor_sync(0xffffffffu, rs1, 1);
        rs1 += __shfl_xor_sync(0xffffffffu, rs1, 2);
        l0 = l0 * f0 + rs0;
        l1 = l1 * f1 + rs1;

        #pragma unroll
        for (int j = 0; j < 8; j++) {
            o[j][0] *= f0; o[j][1] *= f0;
            o[j][2] *= f1; o[j][3] *= f1;
        }

        unsigned ph[4][4], pl[4][4];
        #pragma unroll
        for (int jc = 0; jc < 4; jc++) {
            const int j0 = 2*jc, j1 = 2*jc + 1;
            #define SPLITPAIR(a, b, HI, LOI)                       \
                {  bf16 _h0,_l0,_h1,_l1;                           \
                   split2(a,_h0,_l0); split2(b,_h1,_l1);           \
                   HI  = packbf(__bfloat162float(_h0), __bfloat162float(_h1)); \
                   LOI = packbf(__bfloat162float(_l0), __bfloat162float(_l1)); }
            SPLITPAIR(s[j0][0], s[j0][1], ph[jc][0], pl[jc][0]);
            SPLITPAIR(s[j0][2], s[j0][3], ph[jc][1], pl[jc][1]);
            SPLITPAIR(s[j1][0], s[j1][1], ph[jc][2], pl[jc][2]);
            SPLITPAIR(s[j1][2], s[j1][3], ph[jc][3], pl[jc][3]);
            #undef SPLITPAIR
        }

        #pragma unroll
        for (int jc = 0; jc < 4; jc++) {
            #pragma unroll
            for (int np = 0; np < 4; np++) {
                unsigned vh4[4], vl4[4];
                uint32_t vo = ((jc*16 + vb_r) * AQS + np*16 + vb_c) * 2;
                ldsm4t(vh4, sVh + vo);
                ldsm4t(vl4, sVl + vo);
                mma16816(o[2*np],   ph[jc], vh4);
                mma16816(o[2*np+1], ph[jc], vh4 + 2);
                mma16816(o[2*np],   pl[jc], vh4);
                mma16816(o[2*np+1], pl[jc], vh4 + 2);
                mma16816(o[2*np],   ph[jc], vl4);
                mma16816(o[2*np+1], ph[jc], vl4 + 2);
            }
        }
        __syncthreads();
    }

    const float il0 = 1.0f / l0, il1 = 1.0f / l1;
    const int row0 = tokbase + qt*64 + warp*16 + r0;
    #pragma unroll
    for (int j = 0; j < 8; j++) {
        int c = hcol + j*8 + colq;
        float a0 = o[j][0] * il0, a1 = o[j][1] * il0;
        float b0 = o[j][2] * il1, b1 = o[j][3] * il1;
        bf16 h0,lo0,h1,lo1;
        split2(a0,h0,lo0); split2(a1,h1,lo1);
        bf162 th; th.x = h0; th.y = h1;
        bf162 tl; tl.x = lo0; tl.y = lo1;
        *(bf162*)(zh + (size_t)row0 * DD + c) = th;
        *(bf162*)(zl + (size_t)row0 * DD + c) = tl;
        split2(b0,h0,lo0); split2(b1,h1,lo1);
        th.x = h0; th.y = h1;
        tl.x = lo0; tl.y = lo1;
        *(bf162*)(zh + (size_t)(row0 + 8) * DD + c) = th;
        *(bf162*)(zl + (size_t)(row0 + 8) * DD + c) = tl;
    }
}

// ---------------------------------------------------------------------------
// Host launcher
// ---------------------------------------------------------------------------
extern "C" void kernel_launch(void* const* d_in, const int* in_sizes, int n_in,
                              void* d_out, int out_size)
{
    (void)in_sizes; (void)n_in; (void)out_size;
    const float* resid = (const float*)d_in[0];
    const float* ln1w  = (const float*)d_in[1];
    const float* ln1b  = (const float*)d_in[2];
    const float* WQ    = (const float*)d_in[3];
    const float* bQ    = (const float*)d_in[4];
    const float* WK    = (const float*)d_in[5];
    const float* bK    = (const float*)d_in[6];
    const float* WV    = (const float*)d_in[7];
    const float* bV    = (const float*)d_in[8];
    const float* WO    = (const float*)d_in[9];
    const float* bO    = (const float*)d_in[10];
    const float* ln2w  = (const float*)d_in[11];
    const float* ln2b  = (const float*)d_in[12];
    const float* Win   = (const float*)d_in[13];
    const float* bin   = (const float*)d_in[14];
    const float* Wout  = (const float*)d_in[15];
    const float* bout  = (const float*)d_in[16];

    float *mid, *biasqkv;
    bf16 *xh, *xl, *qkvh, *qkvl, *acth, *actl, *wh, *wl;
    cudaGetSymbolAddress((void**)&mid,   g_mid);
    cudaGetSymbolAddress((void**)&biasqkv, g_bias);
    cudaGetSymbolAddress((void**)&xh,    g_xh);
    cudaGetSymbolAddress((void**)&xl,    g_xl);
    cudaGetSymbolAddress((void**)&qkvh,  g_qkvh);
    cudaGetSymbolAddress((void**)&qkvl,  g_qkvl);
    cudaGetSymbolAddress((void**)&acth,  g_acth);
    cudaGetSymbolAddress((void**)&actl,  g_actl);
    cudaGetSymbolAddress((void**)&wh,    g_wh);
    cudaGetSymbolAddress((void**)&wl,    g_wl);

    cudaFuncSetAttribute(attn_mma, cudaFuncAttributeMaxDynamicSharedMemorySize,
                         ATTN_SMEM);
    cudaFuncSetAttribute(gemm_bf16<EPI_QKV>,
                         cudaFuncAttributeMaxDynamicSharedMemorySize, GEMM_SMEM);
    cudaFuncSetAttribute(gemm_bf16<EPI_BIAS_GELU>,
                         cudaFuncAttributeMaxDynamicSharedMemorySize, GEMM_SMEM);
    cudaFuncSetAttribute(gemm_bf16<EPI_BIAS_RES>,
                         cudaFuncAttributeMaxDynamicSharedMemorySize, GEMM_SMEM);

    dim3 tb(32, 8);

    // 1) LN1 -> split
    ln_split_kernel<<<NTOK, 256>>>(resid, ln1w, ln1b, xh, xl);

    // 2) fused QKV
    concat_bias<<<12, 256>>>(bQ, bK, bV, biasqkv);
    tsplit_qkv<<<dim3(DHH/32, DD/32, 48), tb>>>(WQ, WK, WV, wh, wl);
    dim3 g3072(3*DD/128, NTOK/128);
    gemm_bf16<EPI_QKV><<<g3072, 256, GEMM_SMEM>>>(xh, xl, wh, wl, biasqkv,
                                                  nullptr, nullptr, qkvh, qkvl,
                                                  NTOK, 3*DD, DD);

    // 3) tensor-core causal attention -> z split (into xh/xl)
    dim3 ga(SS / 64, BB * HH);
    attn_mma<<<ga, 128, ATTN_SMEM>>>(qkvh, qkvl, xh, xl);

    // 4) O-projection + residual -> mid
    dim3 g1024(DD/128, NTOK/128);
    tsplit_kernel<<<dim3(DD/32, DD/32, 1), tb>>>(WO, wh, wl, DD, DD);
    gemm_bf16<EPI_BIAS_RES><<<g1024, 256, GEMM_SMEM>>>(xh, xl, wh, wl, bO, resid,
                                                       mid, nullptr, nullptr,
                                                       NTOK, DD, DD);

    // 5) LN2 -> split
    ln_split_kernel<<<NTOK, 256>>>(mid, ln2w, ln2b, xh, xl);

    // 6) MLP in + exact GELU -> split act
    dim3 g4096(DMM/128, NTOK/128);
    tsplit_kernel<<<dim3(DMM/32, DD/32, 1), tb>>>(Win, wh, wl, DD, DMM);
    gemm_bf16<EPI_BIAS_GELU><<<g4096, 256, GEMM_SMEM>>>(xh, xl, wh, wl, bin,
                                                        nullptr, nullptr,
                                                        acth, actl,
                                                        NTOK, DMM, DD);

    // 7) MLP out + bias + residual -> d_out
    tsplit_kernel<<<dim3(DD/32, DMM/32, 1), tb>>>(Wout, wh, wl, DMM, DD);
    gemm_bf16<EPI_BIAS_RES><<<g1024, 256, GEMM_SMEM>>>(acth, actl, wh, wl, bout,
                                                       mid, (float*)d_out,
                                                       nullptr, nullptr,
                                                       NTOK, DD, DMM);
}